// round 12
// baseline (speedup 1.0000x reference)
#include <cuda_runtime.h>
#include <cuda_bf16.h>
#include <math.h>
#include <stdint.h>

#define T 1024
#define DIM 512
#define ED 1024
#define HID 256
#define NE 8
#define NM 325
#define TOPM 8
#define ECAP 2048
#define MCAP 8192

__device__ float g_eo[T * DIM];
__device__ float g_eo_slot[2][T * DIM];
__device__ float g_mo_slot[TOPM][T * DIM];
__device__ int   g_ecount[NE];
__device__ int   g_elist[NE * ECAP];
__device__ float g_ewt[NE * ECAP];
__device__ int   g_mcount[NM];
__device__ int   g_mlist[NM * MCAP];
__device__ float g_mwt[NM * MCAP];
// bf16 split expert weights + activations
__device__ __nv_bfloat16 g_w1h[NE * ED * DIM];
__device__ __nv_bfloat16 g_w1l[NE * ED * DIM];
__device__ __nv_bfloat16 g_w2h[NE * DIM * ED];
__device__ __nv_bfloat16 g_w2l[NE * DIM * ED];
__device__ __nv_bfloat16 g_xh[T * DIM];
__device__ __nv_bfloat16 g_xl[T * DIM];
__device__ __nv_bfloat16 g_ehh[2 * T * ED];
__device__ __nv_bfloat16 g_ehl[2 * T * ED];

__device__ __forceinline__ float gelu_f(float x) {
    return 0.5f * x * (1.0f + erff(x * 0.70710678118654752f));
}
__device__ __forceinline__ float dot4(float4 a, float4 b) {
    return a.x * b.x + a.y * b.y + a.z * b.z + a.w * b.w;
}
__device__ __forceinline__ uint32_t fbits(float x) { return __float_as_uint(x); }
__device__ __forceinline__ void splitb2(float v0, float v1, uint32_t& hi, uint32_t& lo) {
    __nv_bfloat16 h0 = __float2bfloat16_rn(v0);
    __nv_bfloat16 h1 = __float2bfloat16_rn(v1);
    __nv_bfloat16 l0 = __float2bfloat16_rn(v0 - __bfloat162float(h0));
    __nv_bfloat16 l1 = __float2bfloat16_rn(v1 - __bfloat162float(h1));
    __nv_bfloat162 H = __halves2bfloat162(h0, h1);
    __nv_bfloat162 L = __halves2bfloat162(l0, l1);
    hi = *(uint32_t*)&H;
    lo = *(uint32_t*)&L;
}
__device__ __forceinline__ void mma8(float* c, const uint32_t* a, const uint32_t* b) {
    asm volatile("mma.sync.aligned.m16n8k8.row.col.f32.tf32.tf32.f32 "
                 "{%0,%1,%2,%3}, {%4,%5,%6,%7}, {%8,%9}, {%0,%1,%2,%3};"
                 : "+f"(c[0]), "+f"(c[1]), "+f"(c[2]), "+f"(c[3])
                 : "r"(a[0]), "r"(a[1]), "r"(a[2]), "r"(a[3]), "r"(b[0]), "r"(b[1]));
}
__device__ __forceinline__ void mma16(float* c, const uint32_t* a, const uint32_t* b) {
    asm volatile("mma.sync.aligned.m16n8k16.row.col.f32.bf16.bf16.f32 "
                 "{%0,%1,%2,%3}, {%4,%5,%6,%7}, {%8,%9}, {%0,%1,%2,%3};"
                 : "+f"(c[0]), "+f"(c[1]), "+f"(c[2]), "+f"(c[3])
                 : "r"(a[0]), "r"(a[1]), "r"(a[2]), "r"(a[3]), "r"(b[0]), "r"(b[1]));
}
__device__ __forceinline__ void cp16(float* dst, const void* src) {
    uint32_t d = (uint32_t)__cvta_generic_to_shared(dst);
    asm volatile("cp.async.cg.shared.global [%0], [%1], 16;" :: "r"(d), "l"(src) : "memory");
}
__device__ __forceinline__ void cp_commit() { asm volatile("cp.async.commit_group;" ::: "memory"); }
__device__ __forceinline__ void cp_wait0() { asm volatile("cp.async.wait_group 0;" ::: "memory"); }

// split expert weights into bf16 hi/lo ; first blocks also zero routing counters
__global__ __launch_bounds__(256) void k_splitw(const float* __restrict__ w1,
                                                const float* __restrict__ w2) {
    if (blockIdx.x == 0) {
        int t = threadIdx.x;
        if (t < NE) g_ecount[t] = 0;
    }
    if (blockIdx.x == 1) {
        int t = threadIdx.x;
        if (t < NM) g_mcount[t] = 0;
    }
    if (blockIdx.x == 2 && threadIdx.x < NM - 256) g_mcount[256 + threadIdx.x] = 0;
    size_t i = (size_t)blockIdx.x * 256 + threadIdx.x;  // float4 index
    float4 v = __ldg((const float4*)w1 + i);
    uint2 H, L;
    splitb2(v.x, v.y, H.x, L.x);
    splitb2(v.z, v.w, H.y, L.y);
    ((uint2*)g_w1h)[i] = H;
    ((uint2*)g_w1l)[i] = L;
    v = __ldg((const float4*)w2 + i);
    splitb2(v.x, v.y, H.x, L.x);
    splitb2(v.z, v.w, H.y, L.y);
    ((uint2*)g_w2h)[i] = H;
    ((uint2*)g_w2l)[i] = L;
}

// ======== expert router: warp per token, fused x split ========
__global__ __launch_bounds__(256) void k_erouter(const float* __restrict__ x,
                                                 const float* __restrict__ rw,
                                                 const float* __restrict__ rb) {
    int warp = threadIdx.x >> 5, lane = threadIdx.x & 31;
    int t = blockIdx.x * 8 + warp;
    const float4* xr = (const float4*)(x + (size_t)t * DIM);
    float lg[NE];
#pragma unroll
    for (int e = 0; e < NE; e++) lg[e] = 0.f;
#pragma unroll
    for (int i = 0; i < 4; i++) {
        int q = lane + i * 32;
        float4 xv = __ldg(xr + q);
        uint2 H, L;
        splitb2(xv.x, xv.y, H.x, L.x);
        splitb2(xv.z, xv.w, H.y, L.y);
        ((uint2*)g_xh)[t * 128 + q] = H;
        ((uint2*)g_xl)[t * 128 + q] = L;
#pragma unroll
        for (int e = 0; e < NE; e++)
            lg[e] += dot4(__ldg((const float4*)(rw + (size_t)e * DIM) + q), xv);
    }
#pragma unroll
    for (int off = 16; off; off >>= 1)
#pragma unroll
        for (int e = 0; e < NE; e++) lg[e] += __shfl_xor_sync(0xffffffffu, lg[e], off);
    if (lane == 0) {
#pragma unroll
        for (int e = 0; e < NE; e++) lg[e] += __ldg(rb + e);
        int a = 0;
#pragma unroll
        for (int e = 1; e < NE; e++) if (lg[e] > lg[a]) a = e;
        int b = (a == 0) ? 1 : 0;
#pragma unroll
        for (int e = 0; e < NE; e++) if (e != a && lg[e] > lg[b]) b = e;
        float m = lg[a], s = 0.f;
#pragma unroll
        for (int e = 0; e < NE; e++) s += expf(lg[e] - m);
        float pa = expf(lg[a] - m) / s, pb = expf(lg[b] - m) / s;
        float den = pa + pb + 1e-8f;
        int p0 = atomicAdd(&g_ecount[a], 1);
        g_elist[a * ECAP + p0] = t;
        g_ewt[a * ECAP + p0] = pa / den;
        int p1 = atomicAdd(&g_ecount[b], 1);
        g_elist[b * ECAP + p1] = t | (1 << 16);
        g_ewt[b * ECAP + p1] = pb / den;
    }
}

// ======== expert up (bf16 split): H[64x128] = X[64x512] @ W1seg^T ========
#define EA_XB 2560
#define EA_WBASE 5120
#define EA_WB 5120
#define EA_BYTES (15360 * 4)

__global__ __launch_bounds__(256, 2) void k_eA(const float* __restrict__ b1) {
    int e = blockIdx.x >> 3, hseg = blockIdx.x & 7;
    int cnt = g_ecount[e];
    extern __shared__ float sm[];
    __shared__ int stok[64];
    __shared__ int sfs[64];
    int tid = threadIdx.x, warp = tid >> 5, lane = tid & 31, g = lane >> 2, tg = lane & 3;
    int hbase = hseg * 128;
    const __nv_bfloat16* WH = g_w1h + (size_t)e * ED * DIM + (size_t)hbase * DIM;
    const __nv_bfloat16* WL = g_w1l + (size_t)e * ED * DIM + (size_t)hbase * DIM;

    for (int chunk = blockIdx.y; chunk * 64 < cnt; chunk += gridDim.y) {
        int base = chunk * 64, n = min(64, cnt - base);
        __syncthreads();
        if (tid < 64) {
            if (tid < n) {
                int pk = g_elist[e * ECAP + base + tid];
                int t = pk & 0xffff;
                stok[tid] = t * DIM;
                sfs[tid] = (t * 2 + (pk >> 16)) * ED;
            } else { stok[tid] = 0; sfs[tid] = 0; }
        }
        __syncthreads();
#define EA_STAGE(S, BUF) do { \
            float* Xd = sm + (BUF) * EA_XB; \
            float* Wd = sm + EA_WBASE + (BUF) * EA_WB; \
            int k0 = (S) * 32; \
            _Pragma("unroll") \
            for (int it = 0; it < 2; it++) { \
                int id = tid + it * 256, row = id >> 3, pl = (id >> 2) & 1, part = id & 3; \
                const __nv_bfloat16* src = (pl ? g_xl : g_xh) + stok[row] + k0 + part * 8; \
                cp16(Xd + pl * 1280 + row * 20 + part * 4, src); \
            } \
            _Pragma("unroll") \
            for (int it = 0; it < 4; it++) { \
                int id = tid + it * 256, row = id >> 3, pl = (id >> 2) & 1, part = id & 3; \
                const __nv_bfloat16* src = (pl ? WL : WH) + (size_t)row * DIM + k0 + part * 8; \
                cp16(Wd + pl * 2560 + row * 20 + part * 4, src); \
            } \
        } while (0)
        EA_STAGE(0, 0);
        cp_commit();
        float c[4][2][4];
#pragma unroll
        for (int a = 0; a < 4; a++)
#pragma unroll
            for (int b = 0; b < 2; b++)
#pragma unroll
                for (int r = 0; r < 4; r++) c[a][b][r] = 0.f;
        for (int s = 0; s < 16; s++) {
            cp_wait0();
            __syncthreads();
            if (s < 15) { EA_STAGE(s + 1, (s + 1) & 1); cp_commit(); }
            const float* XH = sm + (s & 1) * EA_XB;
            const float* XL = XH + 1280;
            const float* WHs = sm + EA_WBASE + (s & 1) * EA_WB;
            const float* WLs = WHs + 2560;
#pragma unroll
            for (int kb = 0; kb < 16; kb += 8) {
                uint32_t Ah[4][4], Al[4][4];
#pragma unroll
                for (int mf = 0; mf < 4; mf++) {
                    int r0 = (mf * 16 + g) * 20, r1 = r0 + 160;
                    Ah[mf][0] = fbits(XH[r0 + kb + tg]);
                    Ah[mf][1] = fbits(XH[r1 + kb + tg]);
                    Ah[mf][2] = fbits(XH[r0 + kb + 4 + tg]);
                    Ah[mf][3] = fbits(XH[r1 + kb + 4 + tg]);
                    Al[mf][0] = fbits(XL[r0 + kb + tg]);
                    Al[mf][1] = fbits(XL[r1 + kb + tg]);
                    Al[mf][2] = fbits(XL[r0 + kb + 4 + tg]);
                    Al[mf][3] = fbits(XL[r1 + kb + 4 + tg]);
                }
#pragma unroll
                for (int nj = 0; nj < 2; nj++) {
                    int nr = (warp * 16 + nj * 8 + g) * 20;
                    uint32_t Bh[2], Bl[2];
                    Bh[0] = fbits(WHs[nr + kb + tg]);
                    Bh[1] = fbits(WHs[nr + kb + 4 + tg]);
                    Bl[0] = fbits(WLs[nr + kb + tg]);
                    Bl[1] = fbits(WLs[nr + kb + 4 + tg]);
#pragma unroll
                    for (int mf = 0; mf < 4; mf++) {
                        mma16(c[mf][nj], Ah[mf], Bh);
                        mma16(c[mf][nj], Ah[mf], Bl);
                        mma16(c[mf][nj], Al[mf], Bh);
                    }
                }
            }
        }
        const float* b1e = b1 + (size_t)e * ED + hbase;
#pragma unroll
        for (int mf = 0; mf < 4; mf++)
#pragma unroll
            for (int hf = 0; hf < 2; hf++) {
                int row = mf * 16 + g + 8 * hf;
                if (row < n) {
#pragma unroll
                    for (int nj = 0; nj < 2; nj++) {
                        int colb = warp * 16 + nj * 8 + 2 * tg;
                        float2 bb = __ldg((const float2*)(b1e + colb));
                        float v0 = gelu_f(c[mf][nj][hf * 2 + 0] + bb.x);
                        float v1 = gelu_f(c[mf][nj][hf * 2 + 1] + bb.y);
                        uint32_t hi, lo;
                        splitb2(v0, v1, hi, lo);
                        size_t off = (size_t)sfs[row] + hbase + colb;
                        *(uint32_t*)(g_ehh + off) = hi;
                        *(uint32_t*)(g_ehl + off) = lo;
                    }
                }
            }
    }
#undef EA_STAGE
}

// ======== expert down (bf16 split): Y[32x128] = H[32x1024] @ W2seg^T, M=32 chunks ========
#define EB_XB 1280
#define EB_WBASE 2560
#define EB_WB 5120
#define EB_BYTES (12800 * 4)

__global__ __launch_bounds__(256, 2) void k_eB(const float* __restrict__ b2) {
    int e = blockIdx.x >> 2, nseg = blockIdx.x & 3;
    int cnt = g_ecount[e];
    extern __shared__ float sm[];
    __shared__ int stok[32];
    __shared__ int sslot[32];
    __shared__ int sroff[32];
    __shared__ float swt[32];
    int tid = threadIdx.x, warp = tid >> 5, lane = tid & 31, g = lane >> 2, tg = lane & 3;
    int nbase = nseg * 128;
    const __nv_bfloat16* WH = g_w2h + (size_t)e * DIM * ED + (size_t)nbase * ED;
    const __nv_bfloat16* WL = g_w2l + (size_t)e * DIM * ED + (size_t)nbase * ED;

    for (int chunk = blockIdx.y; chunk * 32 < cnt; chunk += gridDim.y) {
        int base = chunk * 32, n = min(32, cnt - base);
        __syncthreads();
        if (tid < 32) {
            if (tid < n) {
                int pk = g_elist[e * ECAP + base + tid];
                int t = pk & 0xffff, sl = pk >> 16;
                stok[tid] = t * DIM;
                sslot[tid] = sl;
                sroff[tid] = (t * 2 + sl) * ED;
                swt[tid] = g_ewt[e * ECAP + base + tid];
            } else { stok[tid] = 0; sslot[tid] = 0; sroff[tid] = 0; swt[tid] = 0.f; }
        }
        __syncthreads();
#define EB_STAGE(S, BUF) do { \
            float* Xd = sm + (BUF) * EB_XB; \
            float* Wd = sm + EB_WBASE + (BUF) * EB_WB; \
            int k0 = (S) * 32; \
            { \
                int id = tid, row = id >> 3, pl = (id >> 2) & 1, part = id & 3; \
                const __nv_bfloat16* src = (pl ? g_ehl : g_ehh) + sroff[row] + k0 + part * 8; \
                cp16(Xd + pl * 640 + row * 20 + part * 4, src); \
            } \
            _Pragma("unroll") \
            for (int it = 0; it < 4; it++) { \
                int id = tid + it * 256, row = id >> 3, pl = (id >> 2) & 1, part = id & 3; \
                const __nv_bfloat16* src = (pl ? WL : WH) + (size_t)row * ED + k0 + part * 8; \
                cp16(Wd + pl * 2560 + row * 20 + part * 4, src); \
            } \
        } while (0)
        EB_STAGE(0, 0);
        cp_commit();
        float c[2][2][4];
#pragma unroll
        for (int a = 0; a < 2; a++)
#pragma unroll
            for (int b = 0; b < 2; b++)
#pragma unroll
                for (int r = 0; r < 4; r++) c[a][b][r] = 0.f;
        for (int s = 0; s < 32; s++) {
            cp_wait0();
            __syncthreads();
            if (s < 31) { EB_STAGE(s + 1, (s + 1) & 1); cp_commit(); }
            const float* XH = sm + (s & 1) * EB_XB;
            const float* XL = XH + 640;
            const float* WHs = sm + EB_WBASE + (s & 1) * EB_WB;
            const float* WLs = WHs + 2560;
#pragma unroll
            for (int kb = 0; kb < 16; kb += 8) {
                uint32_t Ah[2][4], Al[2][4];
#pragma unroll
                for (int mf = 0; mf < 2; mf++) {
                    int r0 = (mf * 16 + g) * 20, r1 = r0 + 160;
                    Ah[mf][0] = fbits(XH[r0 + kb + tg]);
                    Ah[mf][1] = fbits(XH[r1 + kb + tg]);
                    Ah[mf][2] = fbits(XH[r0 + kb + 4 + tg]);
                    Ah[mf][3] = fbits(XH[r1 + kb + 4 + tg]);
                    Al[mf][0] = fbits(XL[r0 + kb + tg]);
                    Al[mf][1] = fbits(XL[r1 + kb + tg]);
                    Al[mf][2] = fbits(XL[r0 + kb + 4 + tg]);
                    Al[mf][3] = fbits(XL[r1 + kb + 4 + tg]);
                }
#pragma unroll
                for (int nj = 0; nj < 2; nj++) {
                    int nr = (warp * 16 + nj * 8 + g) * 20;
                    uint32_t Bh[2], Bl[2];
                    Bh[0] = fbits(WHs[nr + kb + tg]);
                    Bh[1] = fbits(WHs[nr + kb + 4 + tg]);
                    Bl[0] = fbits(WLs[nr + kb + tg]);
                    Bl[1] = fbits(WLs[nr + kb + 4 + tg]);
#pragma unroll
                    for (int mf = 0; mf < 2; mf++) {
                        mma16(c[mf][nj], Ah[mf], Bh);
                        mma16(c[mf][nj], Ah[mf], Bl);
                        mma16(c[mf][nj], Al[mf], Bh);
                    }
                }
            }
        }
        const float* b2e = b2 + (size_t)e * DIM + nbase;
#pragma unroll
        for (int mf = 0; mf < 2; mf++)
#pragma unroll
            for (int hf = 0; hf < 2; hf++) {
                int row = mf * 16 + g + 8 * hf;
                if (row < n) {
                    float wt = swt[row];
                    float* dst = g_eo_slot[sslot[row]] + (size_t)stok[row] + nbase;
#pragma unroll
                    for (int nj = 0; nj < 2; nj++) {
                        int colb = warp * 16 + nj * 8 + 2 * tg;
                        float2 bb = __ldg((const float2*)(b2e + colb));
                        float2 o;
                        o.x = wt * (c[mf][nj][hf * 2 + 0] + bb.x);
                        o.y = wt * (c[mf][nj][hf * 2 + 1] + bb.y);
                        *(float2*)(dst + colb) = o;
                    }
                }
            }
    }
#undef EB_STAGE
}

// ======== micro router: 8 tokens/block, warp-cooperative coalesced weights ========
__global__ __launch_bounds__(512) void k_mrouter(const float* __restrict__ mw,
                                                 const float* __restrict__ mb) {
    __shared__ float xs[8 * DIM];
    __shared__ float probs[8][NM + 3];
    int t0 = blockIdx.x * 8;
    int tid = threadIdx.x, w = tid >> 5, lane = tid & 31;
    for (int idx = tid; idx < 8 * (DIM / 4); idx += 512) {
        int c = idx >> 7, q = idx & 127;
        int t = t0 + c;
        float4 a = ((const float4*)g_eo_slot[0])[t * 128 + q];
        float4 b = ((const float4*)g_eo_slot[1])[t * 128 + q];
        float4 v = make_float4(a.x + b.x, a.y + b.y, a.z + b.z, a.w + b.w);
        ((float4*)xs)[idx] = v;
        ((float4*)g_eo)[t * 128 + q] = v;
    }
    __syncthreads();
    for (int m = w; m < NM; m += 16) {
        const float4* wr = (const float4*)(mw + (size_t)m * DIM);
        float acc[8];
#pragma unroll
        for (int c = 0; c < 8; c++) acc[c] = 0.f;
#pragma unroll
        for (int i = 0; i < 4; i++) {
            int q = lane + i * 32;
            float4 wv = __ldg(wr + q);
#pragma unroll
            for (int c = 0; c < 8; c++)
                acc[c] += dot4(wv, ((const float4*)xs)[c * 128 + q]);
        }
#pragma unroll
        for (int off = 16; off; off >>= 1)
#pragma unroll
            for (int c = 0; c < 8; c++) acc[c] += __shfl_xor_sync(0xffffffffu, acc[c], off);
        if (lane == 0) {
            float bb = __ldg(mb + m);
#pragma unroll
            for (int c = 0; c < 8; c++) probs[c][m] = acc[c] + bb;
        }
    }
    __syncthreads();
    if (w < 8) {
        float* pr = probs[w];
        float mx = -1e30f;
        for (int i = lane; i < NM; i += 32) mx = fmaxf(mx, pr[i]);
#pragma unroll
        for (int off = 16; off; off >>= 1) mx = fmaxf(mx, __shfl_xor_sync(0xffffffff, mx, off));
        float s = 0.f;
        for (int i = lane; i < NM; i += 32) {
            float p = expf(pr[i] - mx);
            pr[i] = p;
            s += p;
        }
#pragma unroll
        for (int off = 16; off; off >>= 1) s += __shfl_xor_sync(0xffffffff, s, off);
        __syncwarp();
        float vals[TOPM];
        int idxs[TOPM];
#pragma unroll
        for (int k = 0; k < TOPM; k++) {
            float bv = -1e30f;
            int bi = NM;
            for (int i = lane; i < NM; i += 32) {
                float v = pr[i];
                if (v > bv) { bv = v; bi = i; }
            }
#pragma unroll
            for (int off = 16; off; off >>= 1) {
                float ov = __shfl_down_sync(0xffffffff, bv, off);
                int oi = __shfl_down_sync(0xffffffff, bi, off);
                if (ov > bv || (ov == bv && oi < bi)) { bv = ov; bi = oi; }
            }
            bi = __shfl_sync(0xffffffff, bi, 0);
            bv = __shfl_sync(0xffffffff, bv, 0);
            vals[k] = bv;
            idxs[k] = bi;
            if (lane == 0) pr[bi] = -1e30f;
            __syncwarp();
        }
        if (lane == 0) {
            float ssum = 0.f;
#pragma unroll
            for (int k = 0; k < TOPM; k++) ssum += vals[k] / s;
            float den = ssum + 1e-8f;
            int t = t0 + w;
#pragma unroll
            for (int k = 0; k < TOPM; k++) {
                float p = (vals[k] / s) / den;
                int pos = atomicAdd(&g_mcount[idxs[k]], 1);
                g_mlist[idxs[k] * MCAP + pos] = t | (k << 16);
                g_mwt[idxs[k] * MCAP + pos] = p;
            }
        }
    }
}

// ======== fused micro FFN: up (tf32) -> H in smem -> down (tf32) + LN ========
#define MF_XB 640
#define MF_WBASE 1280
#define MF_WB 6144
#define MF_H 13568
#define MF_BYTES (21888 * 4)

__global__ __launch_bounds__(256, 2) void k_mfu(const float* __restrict__ w1,
                                                const float* __restrict__ b1,
                                                const float* __restrict__ w2,
                                                const float* __restrict__ b2,
                                                const float* __restrict__ gg,
                                                const float* __restrict__ bbeta) {
    int e = blockIdx.x;
    int cnt = g_mcount[e];
    extern __shared__ float sm[];
    __shared__ int stok[32];
    __shared__ int sslot[32];
    __shared__ float swt[32];
    __shared__ float red_s[32][33];
    __shared__ float red_q[32][33];
    __shared__ float smu[32];
    __shared__ float srs[32];
    int tid = threadIdx.x, warp = tid >> 5, lane = tid & 31, g = lane >> 2, tg = lane & 3;
    const float* W1 = w1 + (size_t)e * HID * DIM;
    const float* W2 = w2 + (size_t)e * DIM * HID;
    const float* b2e = b2 + (size_t)e * DIM;
    const float* gge = gg + (size_t)e * DIM;
    const float* bbe = bbeta + (size_t)e * DIM;
    float* H = sm + MF_H;

    for (int chunk = blockIdx.y; chunk * 32 < cnt; chunk += gridDim.y) {
        int base = chunk * 32, n = min(32, cnt - base);
        __syncthreads();
        if (tid < 32) {
            if (tid < n) {
                int pk = g_mlist[e * MCAP + base + tid];
                stok[tid] = (pk & 0xffff) * DIM;
                sslot[tid] = pk >> 16;
                swt[tid] = g_mwt[e * MCAP + base + tid];
            } else { stok[tid] = 0; sslot[tid] = 0; swt[tid] = 0.f; }
        }
        __syncthreads();
#define UP_STAGE(S, BUF) do { \
            float* Xd = sm + (BUF) * MF_XB; \
            float* Wd = sm + MF_WBASE + (BUF) * MF_WB; \
            int k0 = (S) * 16; \
            if (tid < 128) { \
                int row = tid >> 2, part = tid & 3; \
                cp16(Xd + row * 20 + part * 4, g_eo + stok[row] + k0 + part * 4); \
            } \
            _Pragma("unroll") \
            for (int it = 0; it < 4; it++) { \
                int id = tid + it * 256, r2 = id >> 2, p2 = id & 3; \
                cp16(Wd + r2 * 20 + p2 * 4, W1 + (size_t)r2 * DIM + k0 + p2 * 4); \
            } \
        } while (0)
#define DN_STAGE(S, BUF) do { \
            float* Wd = sm + MF_WBASE + (BUF) * MF_WB; \
            int k0 = (S) * 8; \
            _Pragma("unroll") \
            for (int it = 0; it < 4; it++) { \
                int id = tid + it * 256, r2 = id >> 1, p2 = id & 1; \
                cp16(Wd + r2 * 12 + p2 * 4, W2 + (size_t)r2 * HID + k0 + p2 * 4); \
            } \
        } while (0)
        UP_STAGE(0, 0);
        cp_commit();
        float c1[2][4][4];
#pragma unroll
        for (int a = 0; a < 2; a++)
#pragma unroll
            for (int b = 0; b < 4; b++)
#pragma unroll
                for (int r = 0; r < 4; r++) c1[a][b][r] = 0.f;
        for (int s = 0; s < 32; s++) {
            cp_wait0();
            __syncthreads();
            if (s < 31) { UP_STAGE(s + 1, (s + 1) & 1); cp_commit(); }
            else       { DN_STAGE(0, 0); cp_commit(); }
            const float* Xb = sm + (s & 1) * MF_XB;
            const float* Wb = sm + MF_WBASE + (s & 1) * MF_WB;
#pragma unroll
            for (int kk = 0; kk < 16; kk += 8) {
                uint32_t A[2][4];
#pragma unroll
                for (int mf = 0; mf < 2; mf++) {
                    int r0 = (mf * 16 + g) * 20, r1 = r0 + 160;
                    A[mf][0] = fbits(Xb[r0 + kk + tg]);
                    A[mf][1] = fbits(Xb[r1 + kk + tg]);
                    A[mf][2] = fbits(Xb[r0 + kk + 4 + tg]);
                    A[mf][3] = fbits(Xb[r1 + kk + 4 + tg]);
                }
#pragma unroll
                for (int nj = 0; nj < 4; nj++) {
                    int nr = (warp * 32 + nj * 8 + g) * 20;
                    uint32_t B[2];
                    B[0] = fbits(Wb[nr + kk + tg]);
                    B[1] = fbits(Wb[nr + kk + 4 + tg]);
#pragma unroll
                    for (int mf = 0; mf < 2; mf++) mma8(c1[mf][nj], A[mf], B);
                }
            }
        }
        const float* b1e = b1 + (size_t)e * HID;
#pragma unroll
        for (int mf = 0; mf < 2; mf++)
#pragma unroll
            for (int hf = 0; hf < 2; hf++) {
                int row = mf * 16 + g + 8 * hf;
#pragma unroll
                for (int nj = 0; nj < 4; nj++) {
                    int col = warp * 32 + nj * 8 + 2 * tg;
                    float2 bb = __ldg((const float2*)(b1e + col));
                    H[row * 260 + col] = gelu_f(c1[mf][nj][hf * 2 + 0] + bb.x);
                    H[row * 260 + col + 1] = gelu_f(c1[mf][nj][hf * 2 + 1] + bb.y);
                }
            }
        float c2[2][8][4];
#pragma unroll
        for (int a = 0; a < 2; a++)
#pragma unroll
            for (int b = 0; b < 8; b++)
#pragma unroll
                for (int r = 0; r < 4; r++) c2[a][b][r] = 0.f;
        for (int s = 0; s < 32; s++) {
            cp_wait0();
            __syncthreads();
            if (s < 31) { DN_STAGE(s + 1, (s + 1) & 1); cp_commit(); }
            int k0 = s * 8;
            const float* Wb = sm + MF_WBASE + (s & 1) * MF_WB;
            uint32_t A[2][4];
#pragma unroll
            for (int mf = 0; mf < 2; mf++) {
                int r0 = (mf * 16 + g) * 260, r1 = r0 + 8 * 260;
                A[mf][0] = fbits(H[r0 + k0 + tg]);
                A[mf][1] = fbits(H[r1 + k0 + tg]);
                A[mf][2] = fbits(H[r0 + k0 + 4 + tg]);
                A[mf][3] = fbits(H[r1 + k0 + 4 + tg]);
            }
#pragma unroll
            for (int nj = 0; nj < 8; nj++) {
                int nr = (warp * 64 + nj * 8 + g) * 12;
                uint32_t B[2];
                B[0] = fbits(Wb[nr + tg]);
                B[1] = fbits(Wb[nr + 4 + tg]);
#pragma unroll
                for (int mf = 0; mf < 2; mf++) mma8(c2[mf][nj], A[mf], B);
            }
        }
#pragma unroll
        for (int mf = 0; mf < 2; mf++)
#pragma unroll
            for (int hf = 0; hf < 2; hf++) {
                int row = mf * 16 + g + 8 * hf;
                const float* eop = g_eo + (size_t)stok[row];
                float ps = 0.f, pq = 0.f;
#pragma unroll
                for (int nj = 0; nj < 8; nj++) {
                    int colb = warp * 64 + nj * 8 + 2 * tg;
                    float2 bb = __ldg((const float2*)(b2e + colb));
                    float2 ev = *(const float2*)(eop + colb);
                    float v0 = c2[mf][nj][hf * 2 + 0] + bb.x + ev.x;
                    float v1 = c2[mf][nj][hf * 2 + 1] + bb.y + ev.y;
                    c2[mf][nj][hf * 2 + 0] = v0;
                    c2[mf][nj][hf * 2 + 1] = v1;
                    ps += v0 + v1;
                    pq += v0 * v0 + v1 * v1;
                }
                red_s[row][warp * 4 + tg] = ps;
                red_q[row][warp * 4 + tg] = pq;
            }
        __syncthreads();
#pragma unroll
        for (int rr = 0; rr < 4; rr++) {
            int row = warp * 4 + rr;
            float s1 = red_s[row][lane], q1 = red_q[row][lane];
#pragma unroll
            for (int off = 16; off; off >>= 1) {
                s1 += __shfl_xor_sync(0xffffffff, s1, off);
                q1 += __shfl_xor_sync(0xffffffff, q1, off);
            }
            if (lane == 0) {
                float mu = s1 * (1.0f / DIM);
                smu[row] = mu;
                srs[row] = rsqrtf(q1 * (1.0f / DIM) - mu * mu + 1e-5f);
            }
        }
        __syncthreads();
#pragma unroll
        for (int mf = 0; mf < 2; mf++)
#pragma unroll
            for (int hf = 0; hf < 2; hf++) {
                int row = mf * 16 + g + 8 * hf;
                if (row < n) {
                    float mu = smu[row], rs = srs[row], p = swt[row];
                    float* dst = g_mo_slot[sslot[row]] + (size_t)stok[row];
#pragma unroll
                    for (int nj = 0; nj < 8; nj++) {
                        int colb = warp * 64 + nj * 8 + 2 * tg;
                        float2 gv = __ldg((const float2*)(gge + colb));
                        float2 bv = __ldg((const float2*)(bbe + colb));
                        float2 o;
                        o.x = p * ((c2[mf][nj][hf * 2 + 0] - mu) * rs * gv.x + bv.x);
                        o.y = p * ((c2[mf][nj][hf * 2 + 1] - mu) * rs * gv.y + bv.y);
                        *(float2*)(dst + colb) = o;
                    }
                }
            }
        __syncthreads();
#undef UP_STAGE
#undef DN_STAGE
    }
}

// ======== final combine + LN ========
__global__ __launch_bounds__(256) void k_final(const float* __restrict__ ng,
                                               const float* __restrict__ nb,
                                               float* __restrict__ out) {
    int t = blockIdx.x;
    int tid = threadIdx.x;
    __shared__ float rsum[8], rsq[8];
    __shared__ float smu, srstd;
    float v[2];
#pragma unroll
    for (int j = 0; j < 2; j++) {
        int d = tid + j * 256;
        float c = g_eo[(size_t)t * DIM + d];
        float mo = 0.f;
#pragma unroll
        for (int k = 0; k < TOPM; k++) mo += g_mo_slot[k][(size_t)t * DIM + d];
        v[j] = c + 0.1f * mo;
    }
    float s = v[0] + v[1];
    float q = v[0] * v[0] + v[1] * v[1];
#pragma unroll
    for (int off = 16; off; off >>= 1) {
        s += __shfl_xor_sync(0xffffffff, s, off);
        q += __shfl_xor_sync(0xffffffff, q, off);
    }
    int w = tid >> 5, lane = tid & 31;
    if (lane == 0) { rsum[w] = s; rsq[w] = q; }
    __syncthreads();
    if (tid == 0) {
        float ts = 0.f, tq = 0.f;
#pragma unroll
        for (int i = 0; i < 8; i++) { ts += rsum[i]; tq += rsq[i]; }
        float mu = ts * (1.0f / DIM);
        smu = mu;
        srstd = rsqrtf(tq * (1.0f / DIM) - mu * mu + 1e-5f);
    }
    __syncthreads();
    float mu = smu, rstd = srstd;
#pragma unroll
    for (int j = 0; j < 2; j++) {
        int d = tid + j * 256;
        out[(size_t)t * DIM + d] = (v[j] - mu) * rstd * __ldg(ng + d) + __ldg(nb + d);
    }
}

extern "C" void kernel_launch(void* const* d_in, const int* in_sizes, int n_in,
                              void* d_out, int out_size) {
    const float* x   = (const float*)d_in[0];
    const float* rw  = (const float*)d_in[1];
    const float* rb  = (const float*)d_in[2];
    const float* ew1 = (const float*)d_in[3];
    const float* eb1 = (const float*)d_in[4];
    const float* ew2 = (const float*)d_in[5];
    const float* eb2 = (const float*)d_in[6];
    const float* mrw = (const float*)d_in[7];
    const float* mrb = (const float*)d_in[8];
    const float* mw1 = (const float*)d_in[9];
    const float* mb1 = (const float*)d_in[10];
    const float* mw2 = (const float*)d_in[11];
    const float* mb2 = (const float*)d_in[12];
    const float* mg  = (const float*)d_in[13];
    const float* mbt = (const float*)d_in[14];
    const float* ng  = (const float*)d_in[15];
    const float* nb  = (const float*)d_in[16];
    float* out = (float*)d_out;

    cudaFuncSetAttribute(k_eA, cudaFuncAttributeMaxDynamicSharedMemorySize, EA_BYTES);
    cudaFuncSetAttribute(k_eB, cudaFuncAttributeMaxDynamicSharedMemorySize, EB_BYTES);
    cudaFuncSetAttribute(k_mfu, cudaFuncAttributeMaxDynamicSharedMemorySize, MF_BYTES);

    k_splitw<<<NE * ED * DIM / 4 / 256, 256>>>(ew1, ew2);
    k_erouter<<<T / 8, 256>>>(x, rw, rb);
    k_eA<<<dim3(NE * 8, 8), 256, EA_BYTES>>>(eb1);
    k_eB<<<dim3(NE * 4, 16), 256, EB_BYTES>>>(eb2);
    k_mrouter<<<T / 8, 512>>>(mrw, mrb);
    k_mfu<<<dim3(NM, 2), 256, MF_BYTES>>>(mw1, mb1, mw2, mb2, mg, mbt);
    k_final<<<T, 256>>>(ng, nb, out);
}

// round 14
// speedup vs baseline: 1.2815x; 1.2815x over previous
#include <cuda_runtime.h>
#include <cuda_bf16.h>
#include <math.h>
#include <stdint.h>

#define T 1024
#define DIM 512
#define ED 1024
#define HID 256
#define NE 8
#define NM 325
#define TOPM 8
#define ECAP 2048
#define MCAP 8192

__device__ float g_eo[T * DIM];
__device__ float g_eo_slot[2][T * DIM];
__device__ float g_mo_slot[TOPM][T * DIM];
__device__ int   g_ecount[NE];
__device__ int   g_elist[NE * ECAP];
__device__ float g_ewt[NE * ECAP];
__device__ int   g_mcount[NM];
__device__ int   g_mlist[NM * MCAP];
__device__ float g_mwt[NM * MCAP];
// bf16 split expert weights + activations
__device__ __nv_bfloat16 g_w1h[NE * ED * DIM];
__device__ __nv_bfloat16 g_w1l[NE * ED * DIM];
__device__ __nv_bfloat16 g_w2h[NE * DIM * ED];
__device__ __nv_bfloat16 g_w2l[NE * DIM * ED];
__device__ __nv_bfloat16 g_xh[T * DIM];
__device__ __nv_bfloat16 g_xl[T * DIM];
__device__ __nv_bfloat16 g_ehh[2 * T * ED];
__device__ __nv_bfloat16 g_ehl[2 * T * ED];

__device__ __forceinline__ float gelu_f(float x) {
    return 0.5f * x * (1.0f + erff(x * 0.70710678118654752f));
}
__device__ __forceinline__ float dot4(float4 a, float4 b) {
    return a.x * b.x + a.y * b.y + a.z * b.z + a.w * b.w;
}
__device__ __forceinline__ uint32_t fbits(float x) { return __float_as_uint(x); }
__device__ __forceinline__ void splitb2(float v0, float v1, uint32_t& hi, uint32_t& lo) {
    __nv_bfloat16 h0 = __float2bfloat16_rn(v0);
    __nv_bfloat16 h1 = __float2bfloat16_rn(v1);
    __nv_bfloat16 l0 = __float2bfloat16_rn(v0 - __bfloat162float(h0));
    __nv_bfloat16 l1 = __float2bfloat16_rn(v1 - __bfloat162float(h1));
    __nv_bfloat162 H = __halves2bfloat162(h0, h1);
    __nv_bfloat162 L = __halves2bfloat162(l0, l1);
    hi = *(uint32_t*)&H;
    lo = *(uint32_t*)&L;
}
__device__ __forceinline__ void mma8(float* c, const uint32_t* a, const uint32_t* b) {
    asm volatile("mma.sync.aligned.m16n8k8.row.col.f32.tf32.tf32.f32 "
                 "{%0,%1,%2,%3}, {%4,%5,%6,%7}, {%8,%9}, {%0,%1,%2,%3};"
                 : "+f"(c[0]), "+f"(c[1]), "+f"(c[2]), "+f"(c[3])
                 : "r"(a[0]), "r"(a[1]), "r"(a[2]), "r"(a[3]), "r"(b[0]), "r"(b[1]));
}
__device__ __forceinline__ void mma16(float* c, const uint32_t* a, const uint32_t* b) {
    asm volatile("mma.sync.aligned.m16n8k16.row.col.f32.bf16.bf16.f32 "
                 "{%0,%1,%2,%3}, {%4,%5,%6,%7}, {%8,%9}, {%0,%1,%2,%3};"
                 : "+f"(c[0]), "+f"(c[1]), "+f"(c[2]), "+f"(c[3])
                 : "r"(a[0]), "r"(a[1]), "r"(a[2]), "r"(a[3]), "r"(b[0]), "r"(b[1]));
}
__device__ __forceinline__ void cp16(float* dst, const void* src) {
    uint32_t d = (uint32_t)__cvta_generic_to_shared(dst);
    asm volatile("cp.async.cg.shared.global [%0], [%1], 16;" :: "r"(d), "l"(src) : "memory");
}
__device__ __forceinline__ void cp_commit() { asm volatile("cp.async.commit_group;" ::: "memory"); }
__device__ __forceinline__ void cp_wait0() { asm volatile("cp.async.wait_group 0;" ::: "memory"); }

// split expert weights into bf16 hi/lo ; first blocks also zero routing counters
__global__ __launch_bounds__(256) void k_splitw(const float* __restrict__ w1,
                                                const float* __restrict__ w2) {
    if (blockIdx.x == 0) {
        int t = threadIdx.x;
        if (t < NE) g_ecount[t] = 0;
    }
    if (blockIdx.x == 1) {
        int t = threadIdx.x;
        if (t < NM) g_mcount[t] = 0;
    }
    if (blockIdx.x == 2 && threadIdx.x < NM - 256) g_mcount[256 + threadIdx.x] = 0;
    size_t i = (size_t)blockIdx.x * 256 + threadIdx.x;  // float4 index
    float4 v = __ldg((const float4*)w1 + i);
    uint2 H, L;
    splitb2(v.x, v.y, H.x, L.x);
    splitb2(v.z, v.w, H.y, L.y);
    ((uint2*)g_w1h)[i] = H;
    ((uint2*)g_w1l)[i] = L;
    v = __ldg((const float4*)w2 + i);
    splitb2(v.x, v.y, H.x, L.x);
    splitb2(v.z, v.w, H.y, L.y);
    ((uint2*)g_w2h)[i] = H;
    ((uint2*)g_w2l)[i] = L;
}

// ======== expert router: warp per token, fused x split ========
__global__ __launch_bounds__(256) void k_erouter(const float* __restrict__ x,
                                                 const float* __restrict__ rw,
                                                 const float* __restrict__ rb) {
    int warp = threadIdx.x >> 5, lane = threadIdx.x & 31;
    int t = blockIdx.x * 8 + warp;
    const float4* xr = (const float4*)(x + (size_t)t * DIM);
    float lg[NE];
#pragma unroll
    for (int e = 0; e < NE; e++) lg[e] = 0.f;
#pragma unroll
    for (int i = 0; i < 4; i++) {
        int q = lane + i * 32;
        float4 xv = __ldg(xr + q);
        uint2 H, L;
        splitb2(xv.x, xv.y, H.x, L.x);
        splitb2(xv.z, xv.w, H.y, L.y);
        ((uint2*)g_xh)[t * 128 + q] = H;
        ((uint2*)g_xl)[t * 128 + q] = L;
#pragma unroll
        for (int e = 0; e < NE; e++)
            lg[e] += dot4(__ldg((const float4*)(rw + (size_t)e * DIM) + q), xv);
    }
#pragma unroll
    for (int off = 16; off; off >>= 1)
#pragma unroll
        for (int e = 0; e < NE; e++) lg[e] += __shfl_xor_sync(0xffffffffu, lg[e], off);
    if (lane == 0) {
#pragma unroll
        for (int e = 0; e < NE; e++) lg[e] += __ldg(rb + e);
        int a = 0;
#pragma unroll
        for (int e = 1; e < NE; e++) if (lg[e] > lg[a]) a = e;
        int b = (a == 0) ? 1 : 0;
#pragma unroll
        for (int e = 0; e < NE; e++) if (e != a && lg[e] > lg[b]) b = e;
        float m = lg[a], s = 0.f;
#pragma unroll
        for (int e = 0; e < NE; e++) s += expf(lg[e] - m);
        float pa = expf(lg[a] - m) / s, pb = expf(lg[b] - m) / s;
        float den = pa + pb + 1e-8f;
        int p0 = atomicAdd(&g_ecount[a], 1);
        g_elist[a * ECAP + p0] = t;
        g_ewt[a * ECAP + p0] = pa / den;
        int p1 = atomicAdd(&g_ecount[b], 1);
        g_elist[b * ECAP + p1] = t | (1 << 16);
        g_ewt[b * ECAP + p1] = pb / den;
    }
}

// ======== expert up (bf16 split): H[64x128] = X[64x512] @ W1seg^T ========
#define EA_XB 2560
#define EA_WBASE 5120
#define EA_WB 5120
#define EA_BYTES (15360 * 4)

__global__ __launch_bounds__(256, 2) void k_eA(const float* __restrict__ b1) {
    int e = blockIdx.x >> 3, hseg = blockIdx.x & 7;
    int cnt = g_ecount[e];
    extern __shared__ float sm[];
    __shared__ int stok[64];
    __shared__ int sfs[64];
    int tid = threadIdx.x, warp = tid >> 5, lane = tid & 31, g = lane >> 2, tg = lane & 3;
    int hbase = hseg * 128;
    const __nv_bfloat16* WH = g_w1h + (size_t)e * ED * DIM + (size_t)hbase * DIM;
    const __nv_bfloat16* WL = g_w1l + (size_t)e * ED * DIM + (size_t)hbase * DIM;

    for (int chunk = blockIdx.y; chunk * 64 < cnt; chunk += gridDim.y) {
        int base = chunk * 64, n = min(64, cnt - base);
        __syncthreads();
        if (tid < 64) {
            if (tid < n) {
                int pk = g_elist[e * ECAP + base + tid];
                int t = pk & 0xffff;
                stok[tid] = t * DIM;
                sfs[tid] = (t * 2 + (pk >> 16)) * ED;
            } else { stok[tid] = 0; sfs[tid] = 0; }
        }
        __syncthreads();
#define EA_STAGE(S, BUF) do { \
            float* Xd = sm + (BUF) * EA_XB; \
            float* Wd = sm + EA_WBASE + (BUF) * EA_WB; \
            int k0 = (S) * 32; \
            _Pragma("unroll") \
            for (int it = 0; it < 2; it++) { \
                int id = tid + it * 256, row = id >> 3, pl = (id >> 2) & 1, part = id & 3; \
                const __nv_bfloat16* src = (pl ? g_xl : g_xh) + stok[row] + k0 + part * 8; \
                cp16(Xd + pl * 1280 + row * 20 + part * 4, src); \
            } \
            _Pragma("unroll") \
            for (int it = 0; it < 4; it++) { \
                int id = tid + it * 256, row = id >> 3, pl = (id >> 2) & 1, part = id & 3; \
                const __nv_bfloat16* src = (pl ? WL : WH) + (size_t)row * DIM + k0 + part * 8; \
                cp16(Wd + pl * 2560 + row * 20 + part * 4, src); \
            } \
        } while (0)
        EA_STAGE(0, 0);
        cp_commit();
        float c[4][2][4];
#pragma unroll
        for (int a = 0; a < 4; a++)
#pragma unroll
            for (int b = 0; b < 2; b++)
#pragma unroll
                for (int r = 0; r < 4; r++) c[a][b][r] = 0.f;
        for (int s = 0; s < 16; s++) {
            cp_wait0();
            __syncthreads();
            if (s < 15) { EA_STAGE(s + 1, (s + 1) & 1); cp_commit(); }
            const float* XH = sm + (s & 1) * EA_XB;
            const float* XL = XH + 1280;
            const float* WHs = sm + EA_WBASE + (s & 1) * EA_WB;
            const float* WLs = WHs + 2560;
#pragma unroll
            for (int kb = 0; kb < 16; kb += 8) {
                uint32_t Ah[4][4], Al[4][4];
#pragma unroll
                for (int mf = 0; mf < 4; mf++) {
                    int r0 = (mf * 16 + g) * 20, r1 = r0 + 160;
                    Ah[mf][0] = fbits(XH[r0 + kb + tg]);
                    Ah[mf][1] = fbits(XH[r1 + kb + tg]);
                    Ah[mf][2] = fbits(XH[r0 + kb + 4 + tg]);
                    Ah[mf][3] = fbits(XH[r1 + kb + 4 + tg]);
                    Al[mf][0] = fbits(XL[r0 + kb + tg]);
                    Al[mf][1] = fbits(XL[r1 + kb + tg]);
                    Al[mf][2] = fbits(XL[r0 + kb + 4 + tg]);
                    Al[mf][3] = fbits(XL[r1 + kb + 4 + tg]);
                }
#pragma unroll
                for (int nj = 0; nj < 2; nj++) {
                    int nr = (warp * 16 + nj * 8 + g) * 20;
                    uint32_t Bh[2], Bl[2];
                    Bh[0] = fbits(WHs[nr + kb + tg]);
                    Bh[1] = fbits(WHs[nr + kb + 4 + tg]);
                    Bl[0] = fbits(WLs[nr + kb + tg]);
                    Bl[1] = fbits(WLs[nr + kb + 4 + tg]);
#pragma unroll
                    for (int mf = 0; mf < 4; mf++) {
                        mma16(c[mf][nj], Ah[mf], Bh);
                        mma16(c[mf][nj], Ah[mf], Bl);
                        mma16(c[mf][nj], Al[mf], Bh);
                    }
                }
            }
        }
        const float* b1e = b1 + (size_t)e * ED + hbase;
#pragma unroll
        for (int mf = 0; mf < 4; mf++)
#pragma unroll
            for (int hf = 0; hf < 2; hf++) {
                int row = mf * 16 + g + 8 * hf;
                if (row < n) {
#pragma unroll
                    for (int nj = 0; nj < 2; nj++) {
                        int colb = warp * 16 + nj * 8 + 2 * tg;
                        float2 bb = __ldg((const float2*)(b1e + colb));
                        float v0 = gelu_f(c[mf][nj][hf * 2 + 0] + bb.x);
                        float v1 = gelu_f(c[mf][nj][hf * 2 + 1] + bb.y);
                        uint32_t hi, lo;
                        splitb2(v0, v1, hi, lo);
                        size_t off = (size_t)sfs[row] + hbase + colb;
                        *(uint32_t*)(g_ehh + off) = hi;
                        *(uint32_t*)(g_ehl + off) = lo;
                    }
                }
            }
    }
#undef EA_STAGE
}

// ======== expert down (bf16 split): Y[64x128] = H[64x1024] @ W2seg^T ========
__global__ __launch_bounds__(256, 2) void k_eB(const float* __restrict__ b2) {
    int e = blockIdx.x >> 2, nseg = blockIdx.x & 3;
    int cnt = g_ecount[e];
    extern __shared__ float sm[];
    __shared__ int stok[64];
    __shared__ int sslot[64];
    __shared__ int sroff[64];
    __shared__ float swt[64];
    int tid = threadIdx.x, warp = tid >> 5, lane = tid & 31, g = lane >> 2, tg = lane & 3;
    int nbase = nseg * 128;
    const __nv_bfloat16* WH = g_w2h + (size_t)e * DIM * ED + (size_t)nbase * ED;
    const __nv_bfloat16* WL = g_w2l + (size_t)e * DIM * ED + (size_t)nbase * ED;

    for (int chunk = blockIdx.y; chunk * 64 < cnt; chunk += gridDim.y) {
        int base = chunk * 64, n = min(64, cnt - base);
        __syncthreads();
        if (tid < 64) {
            if (tid < n) {
                int pk = g_elist[e * ECAP + base + tid];
                int t = pk & 0xffff, sl = pk >> 16;
                stok[tid] = t * DIM;
                sslot[tid] = sl;
                sroff[tid] = (t * 2 + sl) * ED;
                swt[tid] = g_ewt[e * ECAP + base + tid];
            } else { stok[tid] = 0; sslot[tid] = 0; sroff[tid] = 0; swt[tid] = 0.f; }
        }
        __syncthreads();
#define EB_STAGE(S, BUF) do { \
            float* Xd = sm + (BUF) * EA_XB; \
            float* Wd = sm + EA_WBASE + (BUF) * EA_WB; \
            int k0 = (S) * 32; \
            _Pragma("unroll") \
            for (int it = 0; it < 2; it++) { \
                int id = tid + it * 256, row = id >> 3, pl = (id >> 2) & 1, part = id & 3; \
                const __nv_bfloat16* src = (pl ? g_ehl : g_ehh) + sroff[row] + k0 + part * 8; \
                cp16(Xd + pl * 1280 + row * 20 + part * 4, src); \
            } \
            _Pragma("unroll") \
            for (int it = 0; it < 4; it++) { \
                int id = tid + it * 256, row = id >> 3, pl = (id >> 2) & 1, part = id & 3; \
                const __nv_bfloat16* src = (pl ? WL : WH) + (size_t)row * ED + k0 + part * 8; \
                cp16(Wd + pl * 2560 + row * 20 + part * 4, src); \
            } \
        } while (0)
        EB_STAGE(0, 0);
        cp_commit();
        float c[4][2][4];
#pragma unroll
        for (int a = 0; a < 4; a++)
#pragma unroll
            for (int b = 0; b < 2; b++)
#pragma unroll
                for (int r = 0; r < 4; r++) c[a][b][r] = 0.f;
        for (int s = 0; s < 32; s++) {
            cp_wait0();
            __syncthreads();
            if (s < 31) { EB_STAGE(s + 1, (s + 1) & 1); cp_commit(); }
            const float* XH = sm + (s & 1) * EA_XB;
            const float* XL = XH + 1280;
            const float* WHs = sm + EA_WBASE + (s & 1) * EA_WB;
            const float* WLs = WHs + 2560;
#pragma unroll
            for (int kb = 0; kb < 16; kb += 8) {
                uint32_t Ah[4][4], Al[4][4];
#pragma unroll
                for (int mf = 0; mf < 4; mf++) {
                    int r0 = (mf * 16 + g) * 20, r1 = r0 + 160;
                    Ah[mf][0] = fbits(XH[r0 + kb + tg]);
                    Ah[mf][1] = fbits(XH[r1 + kb + tg]);
                    Ah[mf][2] = fbits(XH[r0 + kb + 4 + tg]);
                    Ah[mf][3] = fbits(XH[r1 + kb + 4 + tg]);
                    Al[mf][0] = fbits(XL[r0 + kb + tg]);
                    Al[mf][1] = fbits(XL[r1 + kb + tg]);
                    Al[mf][2] = fbits(XL[r0 + kb + 4 + tg]);
                    Al[mf][3] = fbits(XL[r1 + kb + 4 + tg]);
                }
#pragma unroll
                for (int nj = 0; nj < 2; nj++) {
                    int nr = (warp * 16 + nj * 8 + g) * 20;
                    uint32_t Bh[2], Bl[2];
                    Bh[0] = fbits(WHs[nr + kb + tg]);
                    Bh[1] = fbits(WHs[nr + kb + 4 + tg]);
                    Bl[0] = fbits(WLs[nr + kb + tg]);
                    Bl[1] = fbits(WLs[nr + kb + 4 + tg]);
#pragma unroll
                    for (int mf = 0; mf < 4; mf++) {
                        mma16(c[mf][nj], Ah[mf], Bh);
                        mma16(c[mf][nj], Ah[mf], Bl);
                        mma16(c[mf][nj], Al[mf], Bh);
                    }
                }
            }
        }
        const float* b2e = b2 + (size_t)e * DIM + nbase;
#pragma unroll
        for (int mf = 0; mf < 4; mf++)
#pragma unroll
            for (int hf = 0; hf < 2; hf++) {
                int row = mf * 16 + g + 8 * hf;
                if (row < n) {
                    float wt = swt[row];
                    float* dst = g_eo_slot[sslot[row]] + (size_t)stok[row] + nbase;
#pragma unroll
                    for (int nj = 0; nj < 2; nj++) {
                        int colb = warp * 16 + nj * 8 + 2 * tg;
                        float2 bb = __ldg((const float2*)(b2e + colb));
                        float2 o;
                        o.x = wt * (c[mf][nj][hf * 2 + 0] + bb.x);
                        o.y = wt * (c[mf][nj][hf * 2 + 1] + bb.y);
                        *(float2*)(dst + colb) = o;
                    }
                }
            }
    }
#undef EB_STAGE
}

// ======== micro router: 8 tokens/block, warp-cooperative coalesced weights ========
__global__ __launch_bounds__(512) void k_mrouter(const float* __restrict__ mw,
                                                 const float* __restrict__ mb) {
    __shared__ float xs[8 * DIM];
    __shared__ float probs[8][NM + 3];
    int t0 = blockIdx.x * 8;
    int tid = threadIdx.x, w = tid >> 5, lane = tid & 31;
    for (int idx = tid; idx < 8 * (DIM / 4); idx += 512) {
        int c = idx >> 7, q = idx & 127;
        int t = t0 + c;
        float4 a = ((const float4*)g_eo_slot[0])[t * 128 + q];
        float4 b = ((const float4*)g_eo_slot[1])[t * 128 + q];
        float4 v = make_float4(a.x + b.x, a.y + b.y, a.z + b.z, a.w + b.w);
        ((float4*)xs)[idx] = v;
        ((float4*)g_eo)[t * 128 + q] = v;
    }
    __syncthreads();
    for (int m = w; m < NM; m += 16) {
        const float4* wr = (const float4*)(mw + (size_t)m * DIM);
        float acc[8];
#pragma unroll
        for (int c = 0; c < 8; c++) acc[c] = 0.f;
#pragma unroll
        for (int i = 0; i < 4; i++) {
            int q = lane + i * 32;
            float4 wv = __ldg(wr + q);
#pragma unroll
            for (int c = 0; c < 8; c++)
                acc[c] += dot4(wv, ((const float4*)xs)[c * 128 + q]);
        }
#pragma unroll
        for (int off = 16; off; off >>= 1)
#pragma unroll
            for (int c = 0; c < 8; c++) acc[c] += __shfl_xor_sync(0xffffffffu, acc[c], off);
        if (lane == 0) {
            float bb = __ldg(mb + m);
#pragma unroll
            for (int c = 0; c < 8; c++) probs[c][m] = acc[c] + bb;
        }
    }
    __syncthreads();
    if (w < 8) {
        float* pr = probs[w];
        float mx = -1e30f;
        for (int i = lane; i < NM; i += 32) mx = fmaxf(mx, pr[i]);
#pragma unroll
        for (int off = 16; off; off >>= 1) mx = fmaxf(mx, __shfl_xor_sync(0xffffffff, mx, off));
        float s = 0.f;
        for (int i = lane; i < NM; i += 32) {
            float p = expf(pr[i] - mx);
            pr[i] = p;
            s += p;
        }
#pragma unroll
        for (int off = 16; off; off >>= 1) s += __shfl_xor_sync(0xffffffff, s, off);
        __syncwarp();
        float vals[TOPM];
        int idxs[TOPM];
#pragma unroll
        for (int k = 0; k < TOPM; k++) {
            float bv = -1e30f;
            int bi = NM;
            for (int i = lane; i < NM; i += 32) {
                float v = pr[i];
                if (v > bv) { bv = v; bi = i; }
            }
#pragma unroll
            for (int off = 16; off; off >>= 1) {
                float ov = __shfl_down_sync(0xffffffff, bv, off);
                int oi = __shfl_down_sync(0xffffffff, bi, off);
                if (ov > bv || (ov == bv && oi < bi)) { bv = ov; bi = oi; }
            }
            bi = __shfl_sync(0xffffffff, bi, 0);
            bv = __shfl_sync(0xffffffff, bv, 0);
            vals[k] = bv;
            idxs[k] = bi;
            if (lane == 0) pr[bi] = -1e30f;
            __syncwarp();
        }
        if (lane == 0) {
            float ssum = 0.f;
#pragma unroll
            for (int k = 0; k < TOPM; k++) ssum += vals[k] / s;
            float den = ssum + 1e-8f;
            int t = t0 + w;
#pragma unroll
            for (int k = 0; k < TOPM; k++) {
                float p = (vals[k] / s) / den;
                int pos = atomicAdd(&g_mcount[idxs[k]], 1);
                g_mlist[idxs[k] * MCAP + pos] = t | (k << 16);
                g_mwt[idxs[k] * MCAP + pos] = p;
            }
        }
    }
}

// ======== fused micro FFN: up (tf32) -> H in smem -> down (tf32) + LN ========
#define MF_XB 640
#define MF_WBASE 1280
#define MF_WB 6144
#define MF_H 13568
#define MF_BYTES (21888 * 4)

__global__ __launch_bounds__(256, 2) void k_mfu(const float* __restrict__ w1,
                                                const float* __restrict__ b1,
                                                const float* __restrict__ w2,
                                                const float* __restrict__ b2,
                                                const float* __restrict__ gg,
                                                const float* __restrict__ bbeta) {
    int e = blockIdx.x;
    int cnt = g_mcount[e];
    extern __shared__ float sm[];
    __shared__ int stok[32];
    __shared__ int sslot[32];
    __shared__ float swt[32];
    __shared__ float red_s[32][33];
    __shared__ float red_q[32][33];
    __shared__ float smu[32];
    __shared__ float srs[32];
    int tid = threadIdx.x, warp = tid >> 5, lane = tid & 31, g = lane >> 2, tg = lane & 3;
    const float* W1 = w1 + (size_t)e * HID * DIM;
    const float* W2 = w2 + (size_t)e * DIM * HID;
    const float* b2e = b2 + (size_t)e * DIM;
    const float* gge = gg + (size_t)e * DIM;
    const float* bbe = bbeta + (size_t)e * DIM;
    float* H = sm + MF_H;

    for (int chunk = blockIdx.y; chunk * 32 < cnt; chunk += gridDim.y) {
        int base = chunk * 32, n = min(32, cnt - base);
        __syncthreads();
        if (tid < 32) {
            if (tid < n) {
                int pk = g_mlist[e * MCAP + base + tid];
                stok[tid] = (pk & 0xffff) * DIM;
                sslot[tid] = pk >> 16;
                swt[tid] = g_mwt[e * MCAP + base + tid];
            } else { stok[tid] = 0; sslot[tid] = 0; swt[tid] = 0.f; }
        }
        __syncthreads();
#define UP_STAGE(S, BUF) do { \
            float* Xd = sm + (BUF) * MF_XB; \
            float* Wd = sm + MF_WBASE + (BUF) * MF_WB; \
            int k0 = (S) * 16; \
            if (tid < 128) { \
                int row = tid >> 2, part = tid & 3; \
                cp16(Xd + row * 20 + part * 4, g_eo + stok[row] + k0 + part * 4); \
            } \
            _Pragma("unroll") \
            for (int it = 0; it < 4; it++) { \
                int id = tid + it * 256, r2 = id >> 2, p2 = id & 3; \
                cp16(Wd + r2 * 20 + p2 * 4, W1 + (size_t)r2 * DIM + k0 + p2 * 4); \
            } \
        } while (0)
#define DN_STAGE(S, BUF) do { \
            float* Wd = sm + MF_WBASE + (BUF) * MF_WB; \
            int k0 = (S) * 8; \
            _Pragma("unroll") \
            for (int it = 0; it < 4; it++) { \
                int id = tid + it * 256, r2 = id >> 1, p2 = id & 1; \
                cp16(Wd + r2 * 12 + p2 * 4, W2 + (size_t)r2 * HID + k0 + p2 * 4); \
            } \
        } while (0)
        UP_STAGE(0, 0);
        cp_commit();
        float c1[2][4][4];
#pragma unroll
        for (int a = 0; a < 2; a++)
#pragma unroll
            for (int b = 0; b < 4; b++)
#pragma unroll
                for (int r = 0; r < 4; r++) c1[a][b][r] = 0.f;
        for (int s = 0; s < 32; s++) {
            cp_wait0();
            __syncthreads();
            if (s < 31) { UP_STAGE(s + 1, (s + 1) & 1); cp_commit(); }
            else       { DN_STAGE(0, 0); cp_commit(); }
            const float* Xb = sm + (s & 1) * MF_XB;
            const float* Wb = sm + MF_WBASE + (s & 1) * MF_WB;
#pragma unroll
            for (int kk = 0; kk < 16; kk += 8) {
                uint32_t A[2][4];
#pragma unroll
                for (int mf = 0; mf < 2; mf++) {
                    int r0 = (mf * 16 + g) * 20, r1 = r0 + 160;
                    A[mf][0] = fbits(Xb[r0 + kk + tg]);
                    A[mf][1] = fbits(Xb[r1 + kk + tg]);
                    A[mf][2] = fbits(Xb[r0 + kk + 4 + tg]);
                    A[mf][3] = fbits(Xb[r1 + kk + 4 + tg]);
                }
#pragma unroll
                for (int nj = 0; nj < 4; nj++) {
                    int nr = (warp * 32 + nj * 8 + g) * 20;
                    uint32_t B[2];
                    B[0] = fbits(Wb[nr + kk + tg]);
                    B[1] = fbits(Wb[nr + kk + 4 + tg]);
#pragma unroll
                    for (int mf = 0; mf < 2; mf++) mma8(c1[mf][nj], A[mf], B);
                }
            }
        }
        const float* b1e = b1 + (size_t)e * HID;
#pragma unroll
        for (int mf = 0; mf < 2; mf++)
#pragma unroll
            for (int hf = 0; hf < 2; hf++) {
                int row = mf * 16 + g + 8 * hf;
#pragma unroll
                for (int nj = 0; nj < 4; nj++) {
                    int col = warp * 32 + nj * 8 + 2 * tg;
                    float2 bb = __ldg((const float2*)(b1e + col));
                    H[row * 260 + col] = gelu_f(c1[mf][nj][hf * 2 + 0] + bb.x);
                    H[row * 260 + col + 1] = gelu_f(c1[mf][nj][hf * 2 + 1] + bb.y);
                }
            }
        float c2[2][8][4];
#pragma unroll
        for (int a = 0; a < 2; a++)
#pragma unroll
            for (int b = 0; b < 8; b++)
#pragma unroll
                for (int r = 0; r < 4; r++) c2[a][b][r] = 0.f;
        for (int s = 0; s < 32; s++) {
            cp_wait0();
            __syncthreads();
            if (s < 31) { DN_STAGE(s + 1, (s + 1) & 1); cp_commit(); }
            int k0 = s * 8;
            const float* Wb = sm + MF_WBASE + (s & 1) * MF_WB;
            uint32_t A[2][4];
#pragma unroll
            for (int mf = 0; mf < 2; mf++) {
                int r0 = (mf * 16 + g) * 260, r1 = r0 + 8 * 260;
                A[mf][0] = fbits(H[r0 + k0 + tg]);
                A[mf][1] = fbits(H[r1 + k0 + tg]);
                A[mf][2] = fbits(H[r0 + k0 + 4 + tg]);
                A[mf][3] = fbits(H[r1 + k0 + 4 + tg]);
            }
#pragma unroll
            for (int nj = 0; nj < 8; nj++) {
                int nr = (warp * 64 + nj * 8 + g) * 12;
                uint32_t B[2];
                B[0] = fbits(Wb[nr + tg]);
                B[1] = fbits(Wb[nr + 4 + tg]);
#pragma unroll
                for (int mf = 0; mf < 2; mf++) mma8(c2[mf][nj], A[mf], B);
            }
        }
#pragma unroll
        for (int mf = 0; mf < 2; mf++)
#pragma unroll
            for (int hf = 0; hf < 2; hf++) {
                int row = mf * 16 + g + 8 * hf;
                const float* eop = g_eo + (size_t)stok[row];
                float ps = 0.f, pq = 0.f;
#pragma unroll
                for (int nj = 0; nj < 8; nj++) {
                    int colb = warp * 64 + nj * 8 + 2 * tg;
                    float2 bb = __ldg((const float2*)(b2e + colb));
                    float2 ev = *(const float2*)(eop + colb);
                    float v0 = c2[mf][nj][hf * 2 + 0] + bb.x + ev.x;
                    float v1 = c2[mf][nj][hf * 2 + 1] + bb.y + ev.y;
                    c2[mf][nj][hf * 2 + 0] = v0;
                    c2[mf][nj][hf * 2 + 1] = v1;
                    ps += v0 + v1;
                    pq += v0 * v0 + v1 * v1;
                }
                red_s[row][warp * 4 + tg] = ps;
                red_q[row][warp * 4 + tg] = pq;
            }
        __syncthreads();
#pragma unroll
        for (int rr = 0; rr < 4; rr++) {
            int row = warp * 4 + rr;
            float s1 = red_s[row][lane], q1 = red_q[row][lane];
#pragma unroll
            for (int off = 16; off; off >>= 1) {
                s1 += __shfl_xor_sync(0xffffffff, s1, off);
                q1 += __shfl_xor_sync(0xffffffff, q1, off);
            }
            if (lane == 0) {
                float mu = s1 * (1.0f / DIM);
                smu[row] = mu;
                srs[row] = rsqrtf(q1 * (1.0f / DIM) - mu * mu + 1e-5f);
            }
        }
        __syncthreads();
#pragma unroll
        for (int mf = 0; mf < 2; mf++)
#pragma unroll
            for (int hf = 0; hf < 2; hf++) {
                int row = mf * 16 + g + 8 * hf;
                if (row < n) {
                    float mu = smu[row], rs = srs[row], p = swt[row];
                    float* dst = g_mo_slot[sslot[row]] + (size_t)stok[row];
#pragma unroll
                    for (int nj = 0; nj < 8; nj++) {
                        int colb = warp * 64 + nj * 8 + 2 * tg;
                        float2 gv = __ldg((const float2*)(gge + colb));
                        float2 bv = __ldg((const float2*)(bbe + colb));
                        float2 o;
                        o.x = p * ((c2[mf][nj][hf * 2 + 0] - mu) * rs * gv.x + bv.x);
                        o.y = p * ((c2[mf][nj][hf * 2 + 1] - mu) * rs * gv.y + bv.y);
                        *(float2*)(dst + colb) = o;
                    }
                }
            }
        __syncthreads();
#undef UP_STAGE
#undef DN_STAGE
    }
}

// ======== final combine + LN ========
__global__ __launch_bounds__(256) void k_final(const float* __restrict__ ng,
                                               const float* __restrict__ nb,
                                               float* __restrict__ out) {
    int t = blockIdx.x;
    int tid = threadIdx.x;
    __shared__ float rsum[8], rsq[8];
    __shared__ float smu, srstd;
    float v[2];
#pragma unroll
    for (int j = 0; j < 2; j++) {
        int d = tid + j * 256;
        float c = g_eo[(size_t)t * DIM + d];
        float mo = 0.f;
#pragma unroll
        for (int k = 0; k < TOPM; k++) mo += g_mo_slot[k][(size_t)t * DIM + d];
        v[j] = c + 0.1f * mo;
    }
    float s = v[0] + v[1];
    float q = v[0] * v[0] + v[1] * v[1];
#pragma unroll
    for (int off = 16; off; off >>= 1) {
        s += __shfl_xor_sync(0xffffffff, s, off);
        q += __shfl_xor_sync(0xffffffff, q, off);
    }
    int w = tid >> 5, lane = tid & 31;
    if (lane == 0) { rsum[w] = s; rsq[w] = q; }
    __syncthreads();
    if (tid == 0) {
        float ts = 0.f, tq = 0.f;
#pragma unroll
        for (int i = 0; i < 8; i++) { ts += rsum[i]; tq += rsq[i]; }
        float mu = ts * (1.0f / DIM);
        smu = mu;
        srstd = rsqrtf(tq * (1.0f / DIM) - mu * mu + 1e-5f);
    }
    __syncthreads();
    float mu = smu, rstd = srstd;
#pragma unroll
    for (int j = 0; j < 2; j++) {
        int d = tid + j * 256;
        out[(size_t)t * DIM + d] = (v[j] - mu) * rstd * __ldg(ng + d) + __ldg(nb + d);
    }
}

extern "C" void kernel_launch(void* const* d_in, const int* in_sizes, int n_in,
                              void* d_out, int out_size) {
    const float* x   = (const float*)d_in[0];
    const float* rw  = (const float*)d_in[1];
    const float* rb  = (const float*)d_in[2];
    const float* ew1 = (const float*)d_in[3];
    const float* eb1 = (const float*)d_in[4];
    const float* ew2 = (const float*)d_in[5];
    const float* eb2 = (const float*)d_in[6];
    const float* mrw = (const float*)d_in[7];
    const float* mrb = (const float*)d_in[8];
    const float* mw1 = (const float*)d_in[9];
    const float* mb1 = (const float*)d_in[10];
    const float* mw2 = (const float*)d_in[11];
    const float* mb2 = (const float*)d_in[12];
    const float* mg  = (const float*)d_in[13];
    const float* mbt = (const float*)d_in[14];
    const float* ng  = (const float*)d_in[15];
    const float* nb  = (const float*)d_in[16];
    float* out = (float*)d_out;

    cudaFuncSetAttribute(k_eA, cudaFuncAttributeMaxDynamicSharedMemorySize, EA_BYTES);
    cudaFuncSetAttribute(k_eB, cudaFuncAttributeMaxDynamicSharedMemorySize, EA_BYTES);
    cudaFuncSetAttribute(k_mfu, cudaFuncAttributeMaxDynamicSharedMemorySize, MF_BYTES);

    k_splitw<<<NE * ED * DIM / 4 / 256, 256>>>(ew1, ew2);
    k_erouter<<<T / 8, 256>>>(x, rw, rb);
    k_eA<<<dim3(NE * 8, 8), 256, EA_BYTES>>>(eb1);
    k_eB<<<dim3(NE * 4, 8), 256, EA_BYTES>>>(eb2);
    k_mrouter<<<T / 8, 512>>>(mrw, mrb);
    k_mfu<<<dim3(NM, 2), 256, MF_BYTES>>>(mw1, mb1, mw2, mb2, mg, mbt);
    k_final<<<T, 256>>>(ng, nb, out);
}

// round 15
// speedup vs baseline: 1.3207x; 1.0306x over previous
#include <cuda_runtime.h>
#include <cuda_bf16.h>
#include <math.h>
#include <stdint.h>

#define T 1024
#define DIM 512
#define ED 1024
#define HID 256
#define NE 8
#define NM 325
#define TOPM 8
#define ECAP 2048
#define MCAP 8192

__device__ float g_eo[T * DIM];
__device__ float g_eo_slot[2][T * DIM];
__device__ float g_mo_slot[TOPM][T * DIM];
__device__ int   g_ecount[NE];
__device__ int   g_elist[NE * ECAP];
__device__ float g_ewt[NE * ECAP];
__device__ int   g_mcount[NM];
__device__ int   g_mlist[NM * MCAP];
__device__ float g_mwt[NM * MCAP];
// bf16 split expert weights + activations
__device__ __nv_bfloat16 g_w1h[NE * ED * DIM];
__device__ __nv_bfloat16 g_w1l[NE * ED * DIM];
__device__ __nv_bfloat16 g_w2h[NE * DIM * ED];
__device__ __nv_bfloat16 g_w2l[NE * DIM * ED];
__device__ __nv_bfloat16 g_xh[T * DIM];
__device__ __nv_bfloat16 g_xl[T * DIM];
__device__ __nv_bfloat16 g_ehh[2 * T * ED];
__device__ __nv_bfloat16 g_ehl[2 * T * ED];

__device__ __forceinline__ float gelu_f(float x) {
    return 0.5f * x * (1.0f + erff(x * 0.70710678118654752f));
}
__device__ __forceinline__ float dot4(float4 a, float4 b) {
    return a.x * b.x + a.y * b.y + a.z * b.z + a.w * b.w;
}
__device__ __forceinline__ uint32_t fbits(float x) { return __float_as_uint(x); }
__device__ __forceinline__ void splitb2(float v0, float v1, uint32_t& hi, uint32_t& lo) {
    __nv_bfloat16 h0 = __float2bfloat16_rn(v0);
    __nv_bfloat16 h1 = __float2bfloat16_rn(v1);
    __nv_bfloat16 l0 = __float2bfloat16_rn(v0 - __bfloat162float(h0));
    __nv_bfloat16 l1 = __float2bfloat16_rn(v1 - __bfloat162float(h1));
    __nv_bfloat162 H = __halves2bfloat162(h0, h1);
    __nv_bfloat162 L = __halves2bfloat162(l0, l1);
    hi = *(uint32_t*)&H;
    lo = *(uint32_t*)&L;
}
__device__ __forceinline__ void mma8(float* c, const uint32_t* a, const uint32_t* b) {
    asm volatile("mma.sync.aligned.m16n8k8.row.col.f32.tf32.tf32.f32 "
                 "{%0,%1,%2,%3}, {%4,%5,%6,%7}, {%8,%9}, {%0,%1,%2,%3};"
                 : "+f"(c[0]), "+f"(c[1]), "+f"(c[2]), "+f"(c[3])
                 : "r"(a[0]), "r"(a[1]), "r"(a[2]), "r"(a[3]), "r"(b[0]), "r"(b[1]));
}
__device__ __forceinline__ void mma16(float* c, const uint32_t* a, const uint32_t* b) {
    asm volatile("mma.sync.aligned.m16n8k16.row.col.f32.bf16.bf16.f32 "
                 "{%0,%1,%2,%3}, {%4,%5,%6,%7}, {%8,%9}, {%0,%1,%2,%3};"
                 : "+f"(c[0]), "+f"(c[1]), "+f"(c[2]), "+f"(c[3])
                 : "r"(a[0]), "r"(a[1]), "r"(a[2]), "r"(a[3]), "r"(b[0]), "r"(b[1]));
}
__device__ __forceinline__ void cp16(float* dst, const void* src) {
    uint32_t d = (uint32_t)__cvta_generic_to_shared(dst);
    asm volatile("cp.async.cg.shared.global [%0], [%1], 16;" :: "r"(d), "l"(src) : "memory");
}
__device__ __forceinline__ void cp_commit() { asm volatile("cp.async.commit_group;" ::: "memory"); }
__device__ __forceinline__ void cp_wait0() { asm volatile("cp.async.wait_group 0;" ::: "memory"); }
__device__ __forceinline__ void cp_wait1() { asm volatile("cp.async.wait_group 1;" ::: "memory"); }

// split expert weights into bf16 hi/lo ; first blocks also zero routing counters
__global__ __launch_bounds__(256) void k_splitw(const float* __restrict__ w1,
                                                const float* __restrict__ w2) {
    if (blockIdx.x == 0) {
        int t = threadIdx.x;
        if (t < NE) g_ecount[t] = 0;
    }
    if (blockIdx.x == 1) {
        int t = threadIdx.x;
        if (t < NM) g_mcount[t] = 0;
    }
    if (blockIdx.x == 2 && threadIdx.x < NM - 256) g_mcount[256 + threadIdx.x] = 0;
    size_t i = (size_t)blockIdx.x * 256 + threadIdx.x;  // float4 index
    float4 v = __ldg((const float4*)w1 + i);
    uint2 H, L;
    splitb2(v.x, v.y, H.x, L.x);
    splitb2(v.z, v.w, H.y, L.y);
    ((uint2*)g_w1h)[i] = H;
    ((uint2*)g_w1l)[i] = L;
    v = __ldg((const float4*)w2 + i);
    splitb2(v.x, v.y, H.x, L.x);
    splitb2(v.z, v.w, H.y, L.y);
    ((uint2*)g_w2h)[i] = H;
    ((uint2*)g_w2l)[i] = L;
}

// ======== expert router: warp per token, fused x split ========
__global__ __launch_bounds__(256) void k_erouter(const float* __restrict__ x,
                                                 const float* __restrict__ rw,
                                                 const float* __restrict__ rb) {
    int warp = threadIdx.x >> 5, lane = threadIdx.x & 31;
    int t = blockIdx.x * 8 + warp;
    const float4* xr = (const float4*)(x + (size_t)t * DIM);
    float lg[NE];
#pragma unroll
    for (int e = 0; e < NE; e++) lg[e] = 0.f;
#pragma unroll
    for (int i = 0; i < 4; i++) {
        int q = lane + i * 32;
        float4 xv = __ldg(xr + q);
        uint2 H, L;
        splitb2(xv.x, xv.y, H.x, L.x);
        splitb2(xv.z, xv.w, H.y, L.y);
        ((uint2*)g_xh)[t * 128 + q] = H;
        ((uint2*)g_xl)[t * 128 + q] = L;
#pragma unroll
        for (int e = 0; e < NE; e++)
            lg[e] += dot4(__ldg((const float4*)(rw + (size_t)e * DIM) + q), xv);
    }
#pragma unroll
    for (int off = 16; off; off >>= 1)
#pragma unroll
        for (int e = 0; e < NE; e++) lg[e] += __shfl_xor_sync(0xffffffffu, lg[e], off);
    if (lane == 0) {
#pragma unroll
        for (int e = 0; e < NE; e++) lg[e] += __ldg(rb + e);
        int a = 0;
#pragma unroll
        for (int e = 1; e < NE; e++) if (lg[e] > lg[a]) a = e;
        int b = (a == 0) ? 1 : 0;
#pragma unroll
        for (int e = 0; e < NE; e++) if (e != a && lg[e] > lg[b]) b = e;
        float m = lg[a], s = 0.f;
#pragma unroll
        for (int e = 0; e < NE; e++) s += expf(lg[e] - m);
        float pa = expf(lg[a] - m) / s, pb = expf(lg[b] - m) / s;
        float den = pa + pb + 1e-8f;
        int p0 = atomicAdd(&g_ecount[a], 1);
        g_elist[a * ECAP + p0] = t;
        g_ewt[a * ECAP + p0] = pa / den;
        int p1 = atomicAdd(&g_ecount[b], 1);
        g_elist[b * ECAP + p1] = t | (1 << 16);
        g_ewt[b * ECAP + p1] = pb / den;
    }
}

// ======== expert up (bf16 split): H[64x128] = X[64x512] @ W1seg^T, 3-stage ring ========
#define EA_XB 2560
#define EA_WBASE 7680
#define EA_WB 5120
#define EA_BYTES (23040 * 4)

__global__ __launch_bounds__(256, 2) void k_eA(const float* __restrict__ b1) {
    int e = blockIdx.x >> 3, hseg = blockIdx.x & 7;
    int cnt = g_ecount[e];
    extern __shared__ float sm[];
    __shared__ int stok[64];
    __shared__ int sfs[64];
    int tid = threadIdx.x, warp = tid >> 5, lane = tid & 31, g = lane >> 2, tg = lane & 3;
    int hbase = hseg * 128;
    const __nv_bfloat16* WH = g_w1h + (size_t)e * ED * DIM + (size_t)hbase * DIM;
    const __nv_bfloat16* WL = g_w1l + (size_t)e * ED * DIM + (size_t)hbase * DIM;

    for (int chunk = blockIdx.y; chunk * 64 < cnt; chunk += gridDim.y) {
        int base = chunk * 64, n = min(64, cnt - base);
        __syncthreads();
        if (tid < 64) {
            if (tid < n) {
                int pk = g_elist[e * ECAP + base + tid];
                int t = pk & 0xffff;
                stok[tid] = t * DIM;
                sfs[tid] = (t * 2 + (pk >> 16)) * ED;
            } else { stok[tid] = 0; sfs[tid] = 0; }
        }
        __syncthreads();
#define EA_STAGE(S, BUF) do { \
            float* Xd = sm + (BUF) * EA_XB; \
            float* Wd = sm + EA_WBASE + (BUF) * EA_WB; \
            int k0 = (S) * 32; \
            _Pragma("unroll") \
            for (int it = 0; it < 2; it++) { \
                int id = tid + it * 256, row = id >> 3, pl = (id >> 2) & 1, part = id & 3; \
                const __nv_bfloat16* src = (pl ? g_xl : g_xh) + stok[row] + k0 + part * 8; \
                cp16(Xd + pl * 1280 + row * 20 + part * 4, src); \
            } \
            _Pragma("unroll") \
            for (int it = 0; it < 4; it++) { \
                int id = tid + it * 256, row = id >> 3, pl = (id >> 2) & 1, part = id & 3; \
                const __nv_bfloat16* src = (pl ? WL : WH) + (size_t)row * DIM + k0 + part * 8; \
                cp16(Wd + pl * 2560 + row * 20 + part * 4, src); \
            } \
        } while (0)
        EA_STAGE(0, 0);
        cp_commit();
        EA_STAGE(1, 1);
        cp_commit();
        float c[4][2][4];
#pragma unroll
        for (int a = 0; a < 4; a++)
#pragma unroll
            for (int b = 0; b < 2; b++)
#pragma unroll
                for (int r = 0; r < 4; r++) c[a][b][r] = 0.f;
        for (int s = 0; s < 16; s++) {
            if (s == 15) cp_wait0(); else cp_wait1();
            __syncthreads();
            if (s + 2 < 16) { EA_STAGE(s + 2, (s + 2) % 3); cp_commit(); }
            const float* XH = sm + (s % 3) * EA_XB;
            const float* XL = XH + 1280;
            const float* WHs = sm + EA_WBASE + (s % 3) * EA_WB;
            const float* WLs = WHs + 2560;
#pragma unroll
            for (int kb = 0; kb < 16; kb += 8) {
                uint32_t Ah[4][4], Al[4][4];
#pragma unroll
                for (int mf = 0; mf < 4; mf++) {
                    int r0 = (mf * 16 + g) * 20, r1 = r0 + 160;
                    Ah[mf][0] = fbits(XH[r0 + kb + tg]);
                    Ah[mf][1] = fbits(XH[r1 + kb + tg]);
                    Ah[mf][2] = fbits(XH[r0 + kb + 4 + tg]);
                    Ah[mf][3] = fbits(XH[r1 + kb + 4 + tg]);
                    Al[mf][0] = fbits(XL[r0 + kb + tg]);
                    Al[mf][1] = fbits(XL[r1 + kb + tg]);
                    Al[mf][2] = fbits(XL[r0 + kb + 4 + tg]);
                    Al[mf][3] = fbits(XL[r1 + kb + 4 + tg]);
                }
#pragma unroll
                for (int nj = 0; nj < 2; nj++) {
                    int nr = (warp * 16 + nj * 8 + g) * 20;
                    uint32_t Bh[2], Bl[2];
                    Bh[0] = fbits(WHs[nr + kb + tg]);
                    Bh[1] = fbits(WHs[nr + kb + 4 + tg]);
                    Bl[0] = fbits(WLs[nr + kb + tg]);
                    Bl[1] = fbits(WLs[nr + kb + 4 + tg]);
#pragma unroll
                    for (int mf = 0; mf < 4; mf++) {
                        mma16(c[mf][nj], Ah[mf], Bh);
                        mma16(c[mf][nj], Ah[mf], Bl);
                        mma16(c[mf][nj], Al[mf], Bh);
                    }
                }
            }
        }
        const float* b1e = b1 + (size_t)e * ED + hbase;
#pragma unroll
        for (int mf = 0; mf < 4; mf++)
#pragma unroll
            for (int hf = 0; hf < 2; hf++) {
                int row = mf * 16 + g + 8 * hf;
                if (row < n) {
#pragma unroll
                    for (int nj = 0; nj < 2; nj++) {
                        int colb = warp * 16 + nj * 8 + 2 * tg;
                        float2 bb = __ldg((const float2*)(b1e + colb));
                        float v0 = gelu_f(c[mf][nj][hf * 2 + 0] + bb.x);
                        float v1 = gelu_f(c[mf][nj][hf * 2 + 1] + bb.y);
                        uint32_t hi, lo;
                        splitb2(v0, v1, hi, lo);
                        size_t off = (size_t)sfs[row] + hbase + colb;
                        *(uint32_t*)(g_ehh + off) = hi;
                        *(uint32_t*)(g_ehl + off) = lo;
                    }
                }
            }
    }
#undef EA_STAGE
}

// ======== expert down (bf16 split): Y[64x128] = H[64x1024] @ W2seg^T, 3-stage ring ========
__global__ __launch_bounds__(256, 2) void k_eB(const float* __restrict__ b2) {
    int e = blockIdx.x >> 2, nseg = blockIdx.x & 3;
    int cnt = g_ecount[e];
    extern __shared__ float sm[];
    __shared__ int stok[64];
    __shared__ int sslot[64];
    __shared__ int sroff[64];
    __shared__ float swt[64];
    int tid = threadIdx.x, warp = tid >> 5, lane = tid & 31, g = lane >> 2, tg = lane & 3;
    int nbase = nseg * 128;
    const __nv_bfloat16* WH = g_w2h + (size_t)e * DIM * ED + (size_t)nbase * ED;
    const __nv_bfloat16* WL = g_w2l + (size_t)e * DIM * ED + (size_t)nbase * ED;

    for (int chunk = blockIdx.y; chunk * 64 < cnt; chunk += gridDim.y) {
        int base = chunk * 64, n = min(64, cnt - base);
        __syncthreads();
        if (tid < 64) {
            if (tid < n) {
                int pk = g_elist[e * ECAP + base + tid];
                int t = pk & 0xffff, sl = pk >> 16;
                stok[tid] = t * DIM;
                sslot[tid] = sl;
                sroff[tid] = (t * 2 + sl) * ED;
                swt[tid] = g_ewt[e * ECAP + base + tid];
            } else { stok[tid] = 0; sslot[tid] = 0; sroff[tid] = 0; swt[tid] = 0.f; }
        }
        __syncthreads();
#define EB_STAGE(S, BUF) do { \
            float* Xd = sm + (BUF) * EA_XB; \
            float* Wd = sm + EA_WBASE + (BUF) * EA_WB; \
            int k0 = (S) * 32; \
            _Pragma("unroll") \
            for (int it = 0; it < 2; it++) { \
                int id = tid + it * 256, row = id >> 3, pl = (id >> 2) & 1, part = id & 3; \
                const __nv_bfloat16* src = (pl ? g_ehl : g_ehh) + sroff[row] + k0 + part * 8; \
                cp16(Xd + pl * 1280 + row * 20 + part * 4, src); \
            } \
            _Pragma("unroll") \
            for (int it = 0; it < 4; it++) { \
                int id = tid + it * 256, row = id >> 3, pl = (id >> 2) & 1, part = id & 3; \
                const __nv_bfloat16* src = (pl ? WL : WH) + (size_t)row * ED + k0 + part * 8; \
                cp16(Wd + pl * 2560 + row * 20 + part * 4, src); \
            } \
        } while (0)
        EB_STAGE(0, 0);
        cp_commit();
        EB_STAGE(1, 1);
        cp_commit();
        float c[4][2][4];
#pragma unroll
        for (int a = 0; a < 4; a++)
#pragma unroll
            for (int b = 0; b < 2; b++)
#pragma unroll
                for (int r = 0; r < 4; r++) c[a][b][r] = 0.f;
        for (int s = 0; s < 32; s++) {
            if (s == 31) cp_wait0(); else cp_wait1();
            __syncthreads();
            if (s + 2 < 32) { EB_STAGE(s + 2, (s + 2) % 3); cp_commit(); }
            const float* XH = sm + (s % 3) * EA_XB;
            const float* XL = XH + 1280;
            const float* WHs = sm + EA_WBASE + (s % 3) * EA_WB;
            const float* WLs = WHs + 2560;
#pragma unroll
            for (int kb = 0; kb < 16; kb += 8) {
                uint32_t Ah[4][4], Al[4][4];
#pragma unroll
                for (int mf = 0; mf < 4; mf++) {
                    int r0 = (mf * 16 + g) * 20, r1 = r0 + 160;
                    Ah[mf][0] = fbits(XH[r0 + kb + tg]);
                    Ah[mf][1] = fbits(XH[r1 + kb + tg]);
                    Ah[mf][2] = fbits(XH[r0 + kb + 4 + tg]);
                    Ah[mf][3] = fbits(XH[r1 + kb + 4 + tg]);
                    Al[mf][0] = fbits(XL[r0 + kb + tg]);
                    Al[mf][1] = fbits(XL[r1 + kb + tg]);
                    Al[mf][2] = fbits(XL[r0 + kb + 4 + tg]);
                    Al[mf][3] = fbits(XL[r1 + kb + 4 + tg]);
                }
#pragma unroll
                for (int nj = 0; nj < 2; nj++) {
                    int nr = (warp * 16 + nj * 8 + g) * 20;
                    uint32_t Bh[2], Bl[2];
                    Bh[0] = fbits(WHs[nr + kb + tg]);
                    Bh[1] = fbits(WHs[nr + kb + 4 + tg]);
                    Bl[0] = fbits(WLs[nr + kb + tg]);
                    Bl[1] = fbits(WLs[nr + kb + 4 + tg]);
#pragma unroll
                    for (int mf = 0; mf < 4; mf++) {
                        mma16(c[mf][nj], Ah[mf], Bh);
                        mma16(c[mf][nj], Ah[mf], Bl);
                        mma16(c[mf][nj], Al[mf], Bh);
                    }
                }
            }
        }
        const float* b2e = b2 + (size_t)e * DIM + nbase;
#pragma unroll
        for (int mf = 0; mf < 4; mf++)
#pragma unroll
            for (int hf = 0; hf < 2; hf++) {
                int row = mf * 16 + g + 8 * hf;
                if (row < n) {
                    float wt = swt[row];
                    float* dst = g_eo_slot[sslot[row]] + (size_t)stok[row] + nbase;
#pragma unroll
                    for (int nj = 0; nj < 2; nj++) {
                        int colb = warp * 16 + nj * 8 + 2 * tg;
                        float2 bb = __ldg((const float2*)(b2e + colb));
                        float2 o;
                        o.x = wt * (c[mf][nj][hf * 2 + 0] + bb.x);
                        o.y = wt * (c[mf][nj][hf * 2 + 1] + bb.y);
                        *(float2*)(dst + colb) = o;
                    }
                }
            }
    }
#undef EB_STAGE
}

// ======== micro router: 8 tokens/block, warp-cooperative coalesced weights ========
__global__ __launch_bounds__(512) void k_mrouter(const float* __restrict__ mw,
                                                 const float* __restrict__ mb) {
    __shared__ float xs[8 * DIM];
    __shared__ float probs[8][NM + 3];
    int t0 = blockIdx.x * 8;
    int tid = threadIdx.x, w = tid >> 5, lane = tid & 31;
    for (int idx = tid; idx < 8 * (DIM / 4); idx += 512) {
        int c = idx >> 7, q = idx & 127;
        int t = t0 + c;
        float4 a = ((const float4*)g_eo_slot[0])[t * 128 + q];
        float4 b = ((const float4*)g_eo_slot[1])[t * 128 + q];
        float4 v = make_float4(a.x + b.x, a.y + b.y, a.z + b.z, a.w + b.w);
        ((float4*)xs)[idx] = v;
        ((float4*)g_eo)[t * 128 + q] = v;
    }
    __syncthreads();
    for (int m = w; m < NM; m += 16) {
        const float4* wr = (const float4*)(mw + (size_t)m * DIM);
        float acc[8];
#pragma unroll
        for (int c = 0; c < 8; c++) acc[c] = 0.f;
#pragma unroll
        for (int i = 0; i < 4; i++) {
            int q = lane + i * 32;
            float4 wv = __ldg(wr + q);
#pragma unroll
            for (int c = 0; c < 8; c++)
                acc[c] += dot4(wv, ((const float4*)xs)[c * 128 + q]);
        }
#pragma unroll
        for (int off = 16; off; off >>= 1)
#pragma unroll
            for (int c = 0; c < 8; c++) acc[c] += __shfl_xor_sync(0xffffffffu, acc[c], off);
        if (lane == 0) {
            float bb = __ldg(mb + m);
#pragma unroll
            for (int c = 0; c < 8; c++) probs[c][m] = acc[c] + bb;
        }
    }
    __syncthreads();
    if (w < 8) {
        float* pr = probs[w];
        float mx = -1e30f;
        for (int i = lane; i < NM; i += 32) mx = fmaxf(mx, pr[i]);
#pragma unroll
        for (int off = 16; off; off >>= 1) mx = fmaxf(mx, __shfl_xor_sync(0xffffffff, mx, off));
        float s = 0.f;
        for (int i = lane; i < NM; i += 32) {
            float p = expf(pr[i] - mx);
            pr[i] = p;
            s += p;
        }
#pragma unroll
        for (int off = 16; off; off >>= 1) s += __shfl_xor_sync(0xffffffff, s, off);
        __syncwarp();
        float vals[TOPM];
        int idxs[TOPM];
#pragma unroll
        for (int k = 0; k < TOPM; k++) {
            float bv = -1e30f;
            int bi = NM;
            for (int i = lane; i < NM; i += 32) {
                float v = pr[i];
                if (v > bv) { bv = v; bi = i; }
            }
#pragma unroll
            for (int off = 16; off; off >>= 1) {
                float ov = __shfl_down_sync(0xffffffff, bv, off);
                int oi = __shfl_down_sync(0xffffffff, bi, off);
                if (ov > bv || (ov == bv && oi < bi)) { bv = ov; bi = oi; }
            }
            bi = __shfl_sync(0xffffffff, bi, 0);
            bv = __shfl_sync(0xffffffff, bv, 0);
            vals[k] = bv;
            idxs[k] = bi;
            if (lane == 0) pr[bi] = -1e30f;
            __syncwarp();
        }
        if (lane == 0) {
            float ssum = 0.f;
#pragma unroll
            for (int k = 0; k < TOPM; k++) ssum += vals[k] / s;
            float den = ssum + 1e-8f;
            int t = t0 + w;
#pragma unroll
            for (int k = 0; k < TOPM; k++) {
                float p = (vals[k] / s) / den;
                int pos = atomicAdd(&g_mcount[idxs[k]], 1);
                g_mlist[idxs[k] * MCAP + pos] = t | (k << 16);
                g_mwt[idxs[k] * MCAP + pos] = p;
            }
        }
    }
}

// ======== fused micro FFN: 3-stage ring; LN scratch aliased into H ========
// floats: X 3x640 @0 ; W 3x5120 @1920 ; H 32x260 @17280 ; total 25600 (102400 B)
#define MF_XB 640
#define MF_WBASE 1920
#define MF_WB 5120
#define MF_H 17280
#define MF_BYTES (25600 * 4)

__global__ __launch_bounds__(256, 2) void k_mfu(const float* __restrict__ w1,
                                                const float* __restrict__ b1,
                                                const float* __restrict__ w2,
                                                const float* __restrict__ b2,
                                                const float* __restrict__ gg,
                                                const float* __restrict__ bbeta) {
    int e = blockIdx.x;
    int cnt = g_mcount[e];
    extern __shared__ float sm[];
    __shared__ int stok[32];
    __shared__ int sslot[32];
    __shared__ float swt[32];
    int tid = threadIdx.x, warp = tid >> 5, lane = tid & 31, g = lane >> 2, tg = lane & 3;
    const float* W1 = w1 + (size_t)e * HID * DIM;
    const float* W2 = w2 + (size_t)e * DIM * HID;
    const float* b2e = b2 + (size_t)e * DIM;
    const float* gge = gg + (size_t)e * DIM;
    const float* bbe = bbeta + (size_t)e * DIM;
    float* H = sm + MF_H;
    // LN scratch aliases H (dead after down loop)
    float* red_s = sm + MF_H;            // [32*33]
    float* red_q = sm + MF_H + 1056;     // [32*33]
    float* smu   = sm + MF_H + 2112;     // [32]
    float* srs   = sm + MF_H + 2144;     // [32]

    for (int chunk = blockIdx.y; chunk * 32 < cnt; chunk += gridDim.y) {
        int base = chunk * 32, n = min(32, cnt - base);
        __syncthreads();
        if (tid < 32) {
            if (tid < n) {
                int pk = g_mlist[e * MCAP + base + tid];
                stok[tid] = (pk & 0xffff) * DIM;
                sslot[tid] = pk >> 16;
                swt[tid] = g_mwt[e * MCAP + base + tid];
            } else { stok[tid] = 0; sslot[tid] = 0; swt[tid] = 0.f; }
        }
        __syncthreads();
#define UP_STAGE(S, BUF) do { \
            float* Xd = sm + (BUF) * MF_XB; \
            float* Wd = sm + MF_WBASE + (BUF) * MF_WB; \
            int k0 = (S) * 16; \
            if (tid < 128) { \
                int row = tid >> 2, part = tid & 3; \
                cp16(Xd + row * 20 + part * 4, g_eo + stok[row] + k0 + part * 4); \
            } \
            _Pragma("unroll") \
            for (int it = 0; it < 4; it++) { \
                int id = tid + it * 256, r2 = id >> 2, p2 = id & 3; \
                cp16(Wd + r2 * 20 + p2 * 4, W1 + (size_t)r2 * DIM + k0 + p2 * 4); \
            } \
        } while (0)
#define DN_STAGE(S, BUF) do { \
            float* Wd = sm + MF_WBASE + (BUF) * MF_WB; \
            int k0 = (S) * 8; \
            _Pragma("unroll") \
            for (int it = 0; it < 4; it++) { \
                int id = tid + it * 256, r2 = id >> 1, p2 = id & 1; \
                cp16(Wd + r2 * 8 + p2 * 4, W2 + (size_t)r2 * HID + k0 + p2 * 4); \
            } \
        } while (0)
        // ---- up phase: 32 rounds, 3-stage ----
        UP_STAGE(0, 0);
        cp_commit();
        UP_STAGE(1, 1);
        cp_commit();
        float c1[2][4][4];
#pragma unroll
        for (int a = 0; a < 2; a++)
#pragma unroll
            for (int b = 0; b < 4; b++)
#pragma unroll
                for (int r = 0; r < 4; r++) c1[a][b][r] = 0.f;
        for (int s = 0; s < 32; s++) {
            if (s == 31) cp_wait0(); else cp_wait1();
            __syncthreads();
            if (s + 2 < 32) { UP_STAGE(s + 2, (s + 2) % 3); cp_commit(); }
            const float* Xb = sm + (s % 3) * MF_XB;
            const float* Wb = sm + MF_WBASE + (s % 3) * MF_WB;
#pragma unroll
            for (int kk = 0; kk < 16; kk += 8) {
                uint32_t A[2][4];
#pragma unroll
                for (int mf = 0; mf < 2; mf++) {
                    int r0 = (mf * 16 + g) * 20, r1 = r0 + 160;
                    A[mf][0] = fbits(Xb[r0 + kk + tg]);
                    A[mf][1] = fbits(Xb[r1 + kk + tg]);
                    A[mf][2] = fbits(Xb[r0 + kk + 4 + tg]);
                    A[mf][3] = fbits(Xb[r1 + kk + 4 + tg]);
                }
#pragma unroll
                for (int nj = 0; nj < 4; nj++) {
                    int nr = (warp * 32 + nj * 8 + g) * 20;
                    uint32_t B[2];
                    B[0] = fbits(Wb[nr + kk + tg]);
                    B[1] = fbits(Wb[nr + kk + 4 + tg]);
#pragma unroll
                    for (int mf = 0; mf < 2; mf++) mma8(c1[mf][nj], A[mf], B);
                }
            }
        }
        // H epilogue
        const float* b1e = b1 + (size_t)e * HID;
#pragma unroll
        for (int mf = 0; mf < 2; mf++)
#pragma unroll
            for (int hf = 0; hf < 2; hf++) {
                int row = mf * 16 + g + 8 * hf;
#pragma unroll
                for (int nj = 0; nj < 4; nj++) {
                    int col = warp * 32 + nj * 8 + 2 * tg;
                    float2 bb = __ldg((const float2*)(b1e + col));
                    H[row * 260 + col] = gelu_f(c1[mf][nj][hf * 2 + 0] + bb.x);
                    H[row * 260 + col + 1] = gelu_f(c1[mf][nj][hf * 2 + 1] + bb.y);
                }
            }
        __syncthreads();  // all up-phase buffer reads done; H complete
        // ---- down phase: 32 rounds, 3-stage ----
        DN_STAGE(0, 0);
        cp_commit();
        DN_STAGE(1, 1);
        cp_commit();
        float c2[2][8][4];
#pragma unroll
        for (int a = 0; a < 2; a++)
#pragma unroll
            for (int b = 0; b < 8; b++)
#pragma unroll
                for (int r = 0; r < 4; r++) c2[a][b][r] = 0.f;
        for (int s = 0; s < 32; s++) {
            if (s == 31) cp_wait0(); else cp_wait1();
            __syncthreads();
            if (s + 2 < 32) { DN_STAGE(s + 2, (s + 2) % 3); cp_commit(); }
            int k0 = s * 8;
            const float* Wb = sm + MF_WBASE + (s % 3) * MF_WB;
            uint32_t A[2][4];
#pragma unroll
            for (int mf = 0; mf < 2; mf++) {
                int r0 = (mf * 16 + g) * 260, r1 = r0 + 8 * 260;
                A[mf][0] = fbits(H[r0 + k0 + tg]);
                A[mf][1] = fbits(H[r1 + k0 + tg]);
                A[mf][2] = fbits(H[r0 + k0 + 4 + tg]);
                A[mf][3] = fbits(H[r1 + k0 + 4 + tg]);
            }
#pragma unroll
            for (int nj = 0; nj < 8; nj++) {
                int nr = (warp * 64 + nj * 8 + g) * 8;
                uint32_t B[2];
                B[0] = fbits(Wb[nr + tg]);
                B[1] = fbits(Wb[nr + 4 + tg]);
#pragma unroll
                for (int mf = 0; mf < 2; mf++) mma8(c2[mf][nj], A[mf], B);
            }
        }
        __syncthreads();  // H dead; red arrays may now alias it
#pragma unroll
        for (int mf = 0; mf < 2; mf++)
#pragma unroll
            for (int hf = 0; hf < 2; hf++) {
                int row = mf * 16 + g + 8 * hf;
                const float* eop = g_eo + (size_t)stok[row];
                float ps = 0.f, pq = 0.f;
#pragma unroll
                for (int nj = 0; nj < 8; nj++) {
                    int colb = warp * 64 + nj * 8 + 2 * tg;
                    float2 bb = __ldg((const float2*)(b2e + colb));
                    float2 ev = *(const float2*)(eop + colb);
                    float v0 = c2[mf][nj][hf * 2 + 0] + bb.x + ev.x;
                    float v1 = c2[mf][nj][hf * 2 + 1] + bb.y + ev.y;
                    c2[mf][nj][hf * 2 + 0] = v0;
                    c2[mf][nj][hf * 2 + 1] = v1;
                    ps += v0 + v1;
                    pq += v0 * v0 + v1 * v1;
                }
                red_s[row * 33 + warp * 4 + tg] = ps;
                red_q[row * 33 + warp * 4 + tg] = pq;
            }
        __syncthreads();
#pragma unroll
        for (int rr = 0; rr < 4; rr++) {
            int row = warp * 4 + rr;
            float s1 = red_s[row * 33 + lane], q1 = red_q[row * 33 + lane];
#pragma unroll
            for (int off = 16; off; off >>= 1) {
                s1 += __shfl_xor_sync(0xffffffff, s1, off);
                q1 += __shfl_xor_sync(0xffffffff, q1, off);
            }
            if (lane == 0) {
                float mu = s1 * (1.0f / DIM);
                smu[row] = mu;
                srs[row] = rsqrtf(q1 * (1.0f / DIM) - mu * mu + 1e-5f);
            }
        }
        __syncthreads();
#pragma unroll
        for (int mf = 0; mf < 2; mf++)
#pragma unroll
            for (int hf = 0; hf < 2; hf++) {
                int row = mf * 16 + g + 8 * hf;
                if (row < n) {
                    float mu = smu[row], rs = srs[row], p = swt[row];
                    float* dst = g_mo_slot[sslot[row]] + (size_t)stok[row];
#pragma unroll
                    for (int nj = 0; nj < 8; nj++) {
                        int colb = warp * 64 + nj * 8 + 2 * tg;
                        float2 gv = __ldg((const float2*)(gge + colb));
                        float2 bv = __ldg((const float2*)(bbe + colb));
                        float2 o;
                        o.x = p * ((c2[mf][nj][hf * 2 + 0] - mu) * rs * gv.x + bv.x);
                        o.y = p * ((c2[mf][nj][hf * 2 + 1] - mu) * rs * gv.y + bv.y);
                        *(float2*)(dst + colb) = o;
                    }
                }
            }
        __syncthreads();
#undef UP_STAGE
#undef DN_STAGE
    }
}

// ======== final combine + LN ========
__global__ __launch_bounds__(256) void k_final(const float* __restrict__ ng,
                                               const float* __restrict__ nb,
                                               float* __restrict__ out) {
    int t = blockIdx.x;
    int tid = threadIdx.x;
    __shared__ float rsum[8], rsq[8];
    __shared__ float smu, srstd;
    float v[2];
#pragma unroll
    for (int j = 0; j < 2; j++) {
        int d = tid + j * 256;
        float c = g_eo[(size_t)t * DIM + d];
        float mo = 0.f;
#pragma unroll
        for (int k = 0; k < TOPM; k++) mo += g_mo_slot[k][(size_t)t * DIM + d];
        v[j] = c + 0.1f * mo;
    }
    float s = v[0] + v[1];
    float q = v[0] * v[0] + v[1] * v[1];
#pragma unroll
    for (int off = 16; off; off >>= 1) {
        s += __shfl_xor_sync(0xffffffff, s, off);
        q += __shfl_xor_sync(0xffffffff, q, off);
    }
    int w = tid >> 5, lane = tid & 31;
    if (lane == 0) { rsum[w] = s; rsq[w] = q; }
    __syncthreads();
    if (tid == 0) {
        float ts = 0.f, tq = 0.f;
#pragma unroll
        for (int i = 0; i < 8; i++) { ts += rsum[i]; tq += rsq[i]; }
        float mu = ts * (1.0f / DIM);
        smu = mu;
        srstd = rsqrtf(tq * (1.0f / DIM) - mu * mu + 1e-5f);
    }
    __syncthreads();
    float mu = smu, rstd = srstd;
#pragma unroll
    for (int j = 0; j < 2; j++) {
        int d = tid + j * 256;
        out[(size_t)t * DIM + d] = (v[j] - mu) * rstd * __ldg(ng + d) + __ldg(nb + d);
    }
}

extern "C" void kernel_launch(void* const* d_in, const int* in_sizes, int n_in,
                              void* d_out, int out_size) {
    const float* x   = (const float*)d_in[0];
    const float* rw  = (const float*)d_in[1];
    const float* rb  = (const float*)d_in[2];
    const float* ew1 = (const float*)d_in[3];
    const float* eb1 = (const float*)d_in[4];
    const float* ew2 = (const float*)d_in[5];
    const float* eb2 = (const float*)d_in[6];
    const float* mrw = (const float*)d_in[7];
    const float* mrb = (const float*)d_in[8];
    const float* mw1 = (const float*)d_in[9];
    const float* mb1 = (const float*)d_in[10];
    const float* mw2 = (const float*)d_in[11];
    const float* mb2 = (const float*)d_in[12];
    const float* mg  = (const float*)d_in[13];
    const float* mbt = (const float*)d_in[14];
    const float* ng  = (const float*)d_in[15];
    const float* nb  = (const float*)d_in[16];
    float* out = (float*)d_out;

    cudaFuncSetAttribute(k_eA, cudaFuncAttributeMaxDynamicSharedMemorySize, EA_BYTES);
    cudaFuncSetAttribute(k_eB, cudaFuncAttributeMaxDynamicSharedMemorySize, EA_BYTES);
    cudaFuncSetAttribute(k_mfu, cudaFuncAttributeMaxDynamicSharedMemorySize, MF_BYTES);

    k_splitw<<<NE * ED * DIM / 4 / 256, 256>>>(ew1, ew2);
    k_erouter<<<T / 8, 256>>>(x, rw, rb);
    k_eA<<<dim3(NE * 8, 8), 256, EA_BYTES>>>(eb1);
    k_eB<<<dim3(NE * 4, 8), 256, EA_BYTES>>>(eb2);
    k_mrouter<<<T / 8, 512>>>(mrw, mrb);
    k_mfu<<<dim3(NM, 2), 256, MF_BYTES>>>(mw1, mb1, mw2, mb2, mg, mbt);
    k_final<<<T, 256>>>(ng, nb, out);
}